// round 3
// baseline (speedup 1.0000x reference)
#include <cuda_runtime.h>
#include <math.h>

#define Bz   2
#define Sq   2048
#define Hh   16
#define Dd   128
#define HID  2048
#define MM   (Bz*Sq)        // 4096

// ---------------- scratch (static device globals; no allocs) ----------------
__device__ float g_q[MM*HID];     // Q projection  [b*s, h*d]
__device__ float g_k[MM*Dd];      // K projection  [b*s, d]
__device__ float g_v[MM*Dd];      // V projection  [b*s, d]
__device__ float g_attn[MM*HID];  // attn output   [b*s, h*d]

// ---------------------------------------------------------------------------
// SGEMM:  C[M,N] = A[M,K] @ W[N,K]^T       (torch Linear: x @ W.T)
// 128x128 block tile, BK=16, 256 threads, 8x8 microtile.
// ---------------------------------------------------------------------------
#define BM 128
#define BN 128
#define BK 16

__global__ __launch_bounds__(256, 2)
void sgemm_tn(const float* __restrict__ A, const float* __restrict__ W,
              float* __restrict__ C, int M, int N, int K)
{
    __shared__ float As[BK][BM + 4];
    __shared__ float Ws[BK][BN + 4];

    const int bm = blockIdx.y * BM;
    const int bn = blockIdx.x * BN;
    const int t  = threadIdx.x;
    const int trow = (t >> 4) * 8;   // 0..120
    const int tcol = (t & 15) * 8;   // 0..120

    float acc[8][8];
    #pragma unroll
    for (int i = 0; i < 8; i++)
        #pragma unroll
        for (int j = 0; j < 8; j++) acc[i][j] = 0.f;

    for (int k0 = 0; k0 < K; k0 += BK) {
        // each thread loads 2 float4 of A and 2 float4 of W (transposed store)
        #pragma unroll
        for (int j = 0; j < 2; j++) {
            int f4 = t + 256 * j;            // 0..511
            int r  = f4 >> 2;                // 0..127
            int kc = (f4 & 3) * 4;           // 0,4,8,12
            float4 va = *(const float4*)&A[(size_t)(bm + r) * K + k0 + kc];
            As[kc + 0][r] = va.x; As[kc + 1][r] = va.y;
            As[kc + 2][r] = va.z; As[kc + 3][r] = va.w;
            float4 vw = *(const float4*)&W[(size_t)(bn + r) * K + k0 + kc];
            Ws[kc + 0][r] = vw.x; Ws[kc + 1][r] = vw.y;
            Ws[kc + 2][r] = vw.z; Ws[kc + 3][r] = vw.w;
        }
        __syncthreads();

        #pragma unroll
        for (int k = 0; k < BK; k++) {
            float a[8], w[8];
            *(float4*)&a[0] = *(float4*)&As[k][trow];
            *(float4*)&a[4] = *(float4*)&As[k][trow + 4];
            *(float4*)&w[0] = *(float4*)&Ws[k][tcol];
            *(float4*)&w[4] = *(float4*)&Ws[k][tcol + 4];
            #pragma unroll
            for (int i = 0; i < 8; i++)
                #pragma unroll
                for (int j = 0; j < 8; j++)
                    acc[i][j] += a[i] * w[j];
        }
        __syncthreads();
    }

    #pragma unroll
    for (int i = 0; i < 8; i++) {
        float* dst = C + (size_t)(bm + trow + i) * N + bn + tcol;
        *(float4*)(dst + 0) = make_float4(acc[i][0], acc[i][1], acc[i][2], acc[i][3]);
        *(float4*)(dst + 4) = make_float4(acc[i][4], acc[i][5], acc[i][6], acc[i][7]);
    }
}

// ---------------------------------------------------------------------------
// Flash attention (fp32), one block = 64 query rows of one (b,h) slice.
// Online softmax over 32 key tiles of 64. Writes g_attn in [b,s,h*d] layout.
// ---------------------------------------------------------------------------
struct AttnSmem {
    float Qs[Dd][68];      // transposed: [d][qrow]
    float Ks[Dd][68];      // transposed: [d][krow]
    float Vs[64][132];     // [krow][d]
    float P[64][68];       // scores / probs
    float maskv[64];
    float rowmax[64];
    float rowsum[64];
    float rowcorr[64];
};

__global__ __launch_bounds__(256)
void attn_kernel(const float* __restrict__ mask)
{
    extern __shared__ char smem_raw[];
    AttnSmem& sm = *reinterpret_cast<AttnSmem*>(smem_raw);

    const int t    = threadIdx.x;
    const int qt   = blockIdx.x;           // q tile, 0..31
    const int bh   = blockIdx.y;           // 0..31
    const int b    = bh / Hh;
    const int h    = bh % Hh;
    const int ty   = t >> 4, tx = t & 15;
    const int w    = t >> 5, lane = t & 31;

    const float* qptr = g_q + (size_t)b * Sq * HID + h * Dd;
    const float* kptr = g_k + (size_t)b * Sq * Dd;
    const float* vptr = g_v + (size_t)b * Sq * Dd;

    // load Q tile transposed (64 rows x 128 d)
    #pragma unroll
    for (int j = 0; j < 8; j++) {
        int idx = t + 256 * j;             // 0..2047
        int r = idx >> 5, dc = (idx & 31) * 4;
        float4 v4 = *(const float4*)(qptr + (size_t)(qt * 64 + r) * HID + dc);
        sm.Qs[dc + 0][r] = v4.x; sm.Qs[dc + 1][r] = v4.y;
        sm.Qs[dc + 2][r] = v4.z; sm.Qs[dc + 3][r] = v4.w;
    }
    if (t < 64) { sm.rowmax[t] = -INFINITY; sm.rowsum[t] = 0.f; }

    float acc[4][8];
    #pragma unroll
    for (int i = 0; i < 4; i++)
        #pragma unroll
        for (int j = 0; j < 8; j++) acc[i][j] = 0.f;

    const float scale = 0.08838834764831845f;   // 1/sqrt(128)
    const float NEG   = -3.402823466e38f;       // finfo(f32).min

    for (int kt = 0; kt < Sq / 64; kt++) {
        __syncthreads();   // previous PV done before overwriting K/V
        #pragma unroll
        for (int j = 0; j < 8; j++) {
            int idx = t + 256 * j;
            int r = idx >> 5, dc = (idx & 31) * 4;
            float4 kv = *(const float4*)(kptr + (size_t)(kt * 64 + r) * Dd + dc);
            sm.Ks[dc + 0][r] = kv.x; sm.Ks[dc + 1][r] = kv.y;
            sm.Ks[dc + 2][r] = kv.z; sm.Ks[dc + 3][r] = kv.w;
            float4 vv = *(const float4*)(vptr + (size_t)(kt * 64 + r) * Dd + dc);
            *(float4*)&sm.Vs[r][dc] = vv;
        }
        if (t < 64) sm.maskv[t] = mask[b * Sq + kt * 64 + t];
        __syncthreads();

        // scores: thread computes rows ty*4..+4, cols tx*4..+4
        float s4[4][4];
        #pragma unroll
        for (int i = 0; i < 4; i++)
            #pragma unroll
            for (int j = 0; j < 4; j++) s4[i][j] = 0.f;

        #pragma unroll 8
        for (int k = 0; k < Dd; k++) {
            float4 a4 = *(float4*)&sm.Qs[k][ty * 4];
            float4 b4 = *(float4*)&sm.Ks[k][tx * 4];
            float a[4] = {a4.x, a4.y, a4.z, a4.w};
            float bb[4] = {b4.x, b4.y, b4.z, b4.w};
            #pragma unroll
            for (int i = 0; i < 4; i++)
                #pragma unroll
                for (int j = 0; j < 4; j++)
                    s4[i][j] += a[i] * bb[j];
        }
        #pragma unroll
        for (int j = 0; j < 4; j++) {
            float mterm = (1.0f - sm.maskv[tx * 4 + j]) * NEG;
            #pragma unroll
            for (int i = 0; i < 4; i++)
                sm.P[ty * 4 + i][tx * 4 + j] = s4[i][j] * scale + mterm;
        }
        __syncthreads();

        // online softmax: warp w owns rows w*8..w*8+7
        #pragma unroll
        for (int rr = 0; rr < 8; rr++) {
            int r = w * 8 + rr;
            float s0 = sm.P[r][lane], s1 = sm.P[r][lane + 32];
            float m = fmaxf(s0, s1);
            #pragma unroll
            for (int off = 16; off; off >>= 1)
                m = fmaxf(m, __shfl_xor_sync(0xffffffffu, m, off));
            float oldm = sm.rowmax[r];
            float newm = fmaxf(oldm, m);
            float p0 = __expf(s0 - newm), p1 = __expf(s1 - newm);
            sm.P[r][lane] = p0; sm.P[r][lane + 32] = p1;
            float ps = p0 + p1;
            #pragma unroll
            for (int off = 16; off; off >>= 1)
                ps += __shfl_xor_sync(0xffffffffu, ps, off);
            if (lane == 0) {
                float corr = __expf(oldm - newm);
                sm.rowcorr[r] = corr;
                sm.rowsum[r]  = sm.rowsum[r] * corr + ps;
                sm.rowmax[r]  = newm;
            }
        }
        __syncthreads();

        // PV: thread owns rows ty*4..+4, cols tx*8..+8
        float cf[4];
        #pragma unroll
        for (int i = 0; i < 4; i++) cf[i] = sm.rowcorr[ty * 4 + i];
        #pragma unroll
        for (int i = 0; i < 4; i++)
            #pragma unroll
            for (int j = 0; j < 8; j++) acc[i][j] *= cf[i];

        #pragma unroll 8
        for (int kk = 0; kk < 64; kk++) {
            float v8[8];
            *(float4*)&v8[0] = *(float4*)&sm.Vs[kk][tx * 8];
            *(float4*)&v8[4] = *(float4*)&sm.Vs[kk][tx * 8 + 4];
            float p[4];
            #pragma unroll
            for (int i = 0; i < 4; i++) p[i] = sm.P[ty * 4 + i][kk];
            #pragma unroll
            for (int i = 0; i < 4; i++)
                #pragma unroll
                for (int j = 0; j < 8; j++)
                    acc[i][j] += p[i] * v8[j];
        }
    }

    // epilogue: normalize and write [b, s, h*d]
    #pragma unroll
    for (int i = 0; i < 4; i++) {
        int r = ty * 4 + i;
        float inv = 1.0f / sm.rowsum[r];
        float* dst = g_attn + ((size_t)b * Sq + qt * 64 + r) * HID + h * Dd + tx * 8;
        float o[8];
        #pragma unroll
        for (int j = 0; j < 8; j++) o[j] = acc[i][j] * inv;
        *(float4*)(dst + 0) = *(float4*)&o[0];
        *(float4*)(dst + 4) = *(float4*)&o[4];
    }
}

// ---------------------------------------------------------------------------
// KV cache broadcast: key/value outputs are k/v replicated over 16 heads.
// ---------------------------------------------------------------------------
__global__ __launch_bounds__(256)
void kv_broadcast(float* __restrict__ out)
{
    int i = blockIdx.x * 256 + threadIdx.x;   // float4 index, 131072 total
    int o = i * 4;
    int b = o / (Sq * Dd);
    int rem = o - b * Sq * Dd;
    int s = rem / Dd;
    int d = rem - s * Dd;
    float4 kv = *(const float4*)&g_k[o];
    float4 vv = *(const float4*)&g_v[o];
    const size_t keybase = (size_t)MM * HID;                       // 8388608
    const size_t valbase = keybase + (size_t)Bz * Hh * Sq * Dd;    // 16777216
    #pragma unroll
    for (int h = 0; h < Hh; h++) {
        size_t idx = (((size_t)b * Hh + h) * Sq + s) * Dd + d;
        *(float4*)&out[keybase + idx] = kv;
        *(float4*)&out[valbase + idx] = vv;
    }
}

// ---------------------------------------------------------------------------
extern "C" void kernel_launch(void* const* d_in, const int* in_sizes, int n_in,
                              void* d_out, int out_size)
{
    const float* hs   = (const float*)d_in[0];
    const float* mask = (const float*)d_in[1];
    const float* Wq   = (const float*)d_in[2];
    const float* Wk   = (const float*)d_in[3];
    const float* Wv   = (const float*)d_in[4];
    const float* Wo   = (const float*)d_in[5];
    float* out = (float*)d_out;

    void *pq, *pk, *pv, *pa;
    cudaGetSymbolAddress(&pq, g_q);
    cudaGetSymbolAddress(&pk, g_k);
    cudaGetSymbolAddress(&pv, g_v);
    cudaGetSymbolAddress(&pa, g_attn);

    cudaFuncSetAttribute(attn_kernel, cudaFuncAttributeMaxDynamicSharedMemorySize,
                         (int)sizeof(AttnSmem));

    dim3 blk(256);
    // Q projection: [4096,2048] = hs @ Wq^T
    sgemm_tn<<<dim3(HID / BN, MM / BM), blk>>>(hs, Wq, (float*)pq, MM, HID, HID);
    // K / V projections: [4096,128]
    sgemm_tn<<<dim3(Dd / BN, MM / BM), blk>>>(hs, Wk, (float*)pk, MM, Dd, HID);
    sgemm_tn<<<dim3(Dd / BN, MM / BM), blk>>>(hs, Wv, (float*)pv, MM, Dd, HID);
    // KV cache broadcast outputs
    kv_broadcast<<<(MM * Dd / 4 + 255) / 256, blk>>>(out);
    // fused attention
    attn_kernel<<<dim3(Sq / 64, Bz * Hh), blk, sizeof(AttnSmem)>>>(mask);
    // output projection -> out[0 : 8388608]
    sgemm_tn<<<dim3(HID / BN, MM / BM), blk>>>((const float*)pa, Wo, out, MM, HID, HID);
}

// round 4
// speedup vs baseline: 1.4386x; 1.4386x over previous
#include <cuda_runtime.h>
#include <math.h>

#define Bz   2
#define Sq   2048
#define Hh   16
#define Dd   128
#define HID  2048
#define MM   (Bz*Sq)        // 4096

// ---------------- scratch (static device globals; no allocs) ----------------
__device__ float g_q[MM*HID];     // Q projection  [b*s, h*d]
__device__ float g_k[MM*Dd];      // K projection  [b*s, d]
__device__ float g_v[MM*Dd];      // V projection  [b*s, d]
__device__ float g_attn[MM*HID];  // attn output   [b*s, h*d]

// ---------------------------------------------------------------------------
// tf32 helpers
// ---------------------------------------------------------------------------
__device__ __forceinline__ void split_tf32(float x, unsigned& hi, unsigned& lo)
{
    unsigned h;
    asm("cvt.rna.tf32.f32 %0, %1;" : "=r"(h) : "f"(x));
    hi = h;
    lo = __float_as_uint(x - __uint_as_float(h));
}

__device__ __forceinline__ void mma_tf32(float c[4],
    unsigned a0, unsigned a1, unsigned a2, unsigned a3,
    unsigned b0, unsigned b1)
{
    asm volatile(
        "mma.sync.aligned.m16n8k8.row.col.f32.tf32.tf32.f32 "
        "{%0,%1,%2,%3}, {%4,%5,%6,%7}, {%8,%9}, {%0,%1,%2,%3};"
        : "+f"(c[0]), "+f"(c[1]), "+f"(c[2]), "+f"(c[3])
        : "r"(a0), "r"(a1), "r"(a2), "r"(a3), "r"(b0), "r"(b1));
}

// ---------------------------------------------------------------------------
// 3xTF32 GEMM:  C[M,N] = A[M,K] @ W[N,K]^T
// 128x128 block, BK=32, 256 threads (8 warps, 4x2), warp tile 32m x 64n.
// ---------------------------------------------------------------------------
#define BM 128
#define BN 128
#define BK 32
#define KST 36   // BK+4 -> stride % 32 == 4 -> conflict-free frag LDS

__global__ __launch_bounds__(256, 1)
void gemm_tf32x3(const float* __restrict__ A, const float* __restrict__ W,
                 float* __restrict__ C, int M, int N, int K)
{
    __shared__ float As[BM][KST];
    __shared__ float Bs[BN][KST];

    const int t    = threadIdx.x;
    const int lane = t & 31, w = t >> 5;
    const int g    = lane >> 2, tig = lane & 3;
    const int wm   = w >> 1;        // 0..3 -> m base wm*32
    const int wn   = w & 1;         // 0..1 -> n base wn*64
    const int bm   = blockIdx.y * BM;
    const int bn   = blockIdx.x * BN;

    float acc[2][8][4];
    #pragma unroll
    for (int i = 0; i < 2; i++)
        #pragma unroll
        for (int j = 0; j < 8; j++)
            #pragma unroll
            for (int q = 0; q < 4; q++) acc[i][j][q] = 0.f;

    for (int k0 = 0; k0 < K; k0 += BK) {
        // fill smem: 128x32 floats each for A and B -> 4 float4 per thread each
        #pragma unroll
        for (int i = 0; i < 4; i++) {
            int f4 = t + 256 * i;          // 0..1023
            int r  = f4 >> 3;              // 0..127
            int kc = (f4 & 7) * 4;         // 0..28
            *(float4*)&As[r][kc] = *(const float4*)&A[(size_t)(bm + r) * K + k0 + kc];
            *(float4*)&Bs[r][kc] = *(const float4*)&W[(size_t)(bn + r) * K + k0 + kc];
        }
        __syncthreads();

        #pragma unroll
        for (int ks = 0; ks < BK / 8; ks++) {
            const int kk = ks * 8;
            // A frags: 2 m16 tiles
            unsigned ah[2][4], al[2][4];
            #pragma unroll
            for (int mt = 0; mt < 2; mt++) {
                int m0 = wm * 32 + mt * 16;
                split_tf32(As[m0 + g    ][kk + tig    ], ah[mt][0], al[mt][0]);
                split_tf32(As[m0 + g + 8][kk + tig    ], ah[mt][1], al[mt][1]);
                split_tf32(As[m0 + g    ][kk + tig + 4], ah[mt][2], al[mt][2]);
                split_tf32(As[m0 + g + 8][kk + tig + 4], ah[mt][3], al[mt][3]);
            }
            // B frags: 8 n8 tiles
            unsigned bh[8][2], bl[8][2];
            #pragma unroll
            for (int nt = 0; nt < 8; nt++) {
                int nc = wn * 64 + nt * 8 + g;
                split_tf32(Bs[nc][kk + tig    ], bh[nt][0], bl[nt][0]);
                split_tf32(Bs[nc][kk + tig + 4], bh[nt][1], bl[nt][1]);
            }
            #pragma unroll
            for (int mt = 0; mt < 2; mt++)
                #pragma unroll
                for (int nt = 0; nt < 8; nt++) {
                    mma_tf32(acc[mt][nt], ah[mt][0], ah[mt][1], ah[mt][2], ah[mt][3], bl[nt][0], bl[nt][1]);
                    mma_tf32(acc[mt][nt], al[mt][0], al[mt][1], al[mt][2], al[mt][3], bh[nt][0], bh[nt][1]);
                    mma_tf32(acc[mt][nt], ah[mt][0], ah[mt][1], ah[mt][2], ah[mt][3], bh[nt][0], bh[nt][1]);
                }
        }
        __syncthreads();
    }

    // epilogue
    #pragma unroll
    for (int mt = 0; mt < 2; mt++) {
        int r0 = bm + wm * 32 + mt * 16 + g;
        #pragma unroll
        for (int nt = 0; nt < 8; nt++) {
            int c0 = bn + wn * 64 + nt * 8 + tig * 2;
            *(float2*)&C[(size_t)r0 * N + c0]       = make_float2(acc[mt][nt][0], acc[mt][nt][1]);
            *(float2*)&C[(size_t)(r0 + 8) * N + c0] = make_float2(acc[mt][nt][2], acc[mt][nt][3]);
        }
    }
}

// ---------------------------------------------------------------------------
// Flash attention with 3xTF32 mma for QK^T and PV.
// Block = 64 q rows of one (b,h); 256 threads (8 warps); 32 key tiles of 64.
// ---------------------------------------------------------------------------
struct AttnSmem {
    float Qs[64][132];   // [qrow][d]   stride%32==4
    float Ks[64][132];   // [krow][d]   stride%32==4
    float Vs[64][136];   // [krow][d]   stride%32==8 (B-operand pattern)
    float P [64][68];    // probs       stride%32==4
    float maskv[64];
    float rowmax[64];
    float rowsum[64];
    float rowcorr[64];
};

__global__ __launch_bounds__(256, 1)
void attn_kernel(const float* __restrict__ mask)
{
    extern __shared__ char smem_raw[];
    AttnSmem& sm = *reinterpret_cast<AttnSmem*>(smem_raw);

    const int t    = threadIdx.x;
    const int lane = t & 31, w = t >> 5;
    const int g    = lane >> 2, tig = lane & 3;
    const int qt   = blockIdx.x;           // 0..31
    const int bh   = blockIdx.y;           // 0..31
    const int b    = bh / Hh;
    const int h    = bh % Hh;

    // QK warp tiling: 4x2 -> warp tile 16m x 32n
    const int wmQ = w >> 1, wnQ = w & 1;
    // PV warp tiling: 2x4 -> warp tile 32m x 32n
    const int wmP = w >> 2, wnP = w & 3;

    const float* qptr = g_q + (size_t)b * Sq * HID + h * Dd;
    const float* kptr = g_k + (size_t)b * Sq * Dd;
    const float* vptr = g_v + (size_t)b * Sq * Dd;

    // load Q tile [64][128]
    #pragma unroll
    for (int j = 0; j < 8; j++) {
        int idx = t + 256 * j;             // 0..2047
        int r = idx >> 5, dc = (idx & 31) * 4;
        *(float4*)&sm.Qs[r][dc] = *(const float4*)(qptr + (size_t)(qt * 64 + r) * HID + dc);
    }
    if (t < 64) { sm.rowmax[t] = -INFINITY; sm.rowsum[t] = 0.f; }

    float pv[2][4][4];
    #pragma unroll
    for (int i = 0; i < 2; i++)
        #pragma unroll
        for (int j = 0; j < 4; j++)
            #pragma unroll
            for (int q = 0; q < 4; q++) pv[i][j][q] = 0.f;

    const float scale = 0.08838834764831845f;   // 1/sqrt(128)
    const float NEG   = -3.402823466e38f;

    for (int kt = 0; kt < Sq / 64; kt++) {
        __syncthreads();   // prior PV done before K/V overwrite
        #pragma unroll
        for (int j = 0; j < 8; j++) {
            int idx = t + 256 * j;
            int r = idx >> 5, dc = (idx & 31) * 4;
            *(float4*)&sm.Ks[r][dc] = *(const float4*)(kptr + (size_t)(kt * 64 + r) * Dd + dc);
            *(float4*)&sm.Vs[r][dc] = *(const float4*)(vptr + (size_t)(kt * 64 + r) * Dd + dc);
        }
        if (t < 64) sm.maskv[t] = mask[b * Sq + kt * 64 + t];
        __syncthreads();

        // ----- QK^T (3xTF32): warp computes 16x32 of the 64x64 score tile
        float cqk[4][4];
        #pragma unroll
        for (int nt = 0; nt < 4; nt++)
            #pragma unroll
            for (int q = 0; q < 4; q++) cqk[nt][q] = 0.f;

        #pragma unroll 4
        for (int ks = 0; ks < Dd / 8; ks++) {
            const int kk = ks * 8;
            int m0 = wmQ * 16;
            unsigned ah[4], al[4];
            split_tf32(sm.Qs[m0 + g    ][kk + tig    ], ah[0], al[0]);
            split_tf32(sm.Qs[m0 + g + 8][kk + tig    ], ah[1], al[1]);
            split_tf32(sm.Qs[m0 + g    ][kk + tig + 4], ah[2], al[2]);
            split_tf32(sm.Qs[m0 + g + 8][kk + tig + 4], ah[3], al[3]);
            #pragma unroll
            for (int nt = 0; nt < 4; nt++) {
                int nc = wnQ * 32 + nt * 8 + g;
                unsigned bh0, bl0, bh1, bl1;
                split_tf32(sm.Ks[nc][kk + tig    ], bh0, bl0);
                split_tf32(sm.Ks[nc][kk + tig + 4], bh1, bl1);
                mma_tf32(cqk[nt], ah[0], ah[1], ah[2], ah[3], bl0, bl1);
                mma_tf32(cqk[nt], al[0], al[1], al[2], al[3], bh0, bh1);
                mma_tf32(cqk[nt], ah[0], ah[1], ah[2], ah[3], bh0, bh1);
            }
        }
        // write scaled + masked scores to P
        #pragma unroll
        for (int nt = 0; nt < 4; nt++) {
            int col = wnQ * 32 + nt * 8 + tig * 2;
            int row = wmQ * 16 + g;
            float mt0 = (1.0f - sm.maskv[col])     * NEG;
            float mt1 = (1.0f - sm.maskv[col + 1]) * NEG;
            sm.P[row    ][col    ] = cqk[nt][0] * scale + mt0;
            sm.P[row    ][col + 1] = cqk[nt][1] * scale + mt1;
            sm.P[row + 8][col    ] = cqk[nt][2] * scale + mt0;
            sm.P[row + 8][col + 1] = cqk[nt][3] * scale + mt1;
        }
        __syncthreads();

        // ----- online softmax: warp w owns rows w*8..w*8+7
        #pragma unroll
        for (int rr = 0; rr < 8; rr++) {
            int r = w * 8 + rr;
            float s0 = sm.P[r][lane], s1 = sm.P[r][lane + 32];
            float m = fmaxf(s0, s1);
            #pragma unroll
            for (int off = 16; off; off >>= 1)
                m = fmaxf(m, __shfl_xor_sync(0xffffffffu, m, off));
            float oldm = sm.rowmax[r];
            float newm = fmaxf(oldm, m);
            float p0 = __expf(s0 - newm), p1 = __expf(s1 - newm);
            sm.P[r][lane] = p0; sm.P[r][lane + 32] = p1;
            float ps = p0 + p1;
            #pragma unroll
            for (int off = 16; off; off >>= 1)
                ps += __shfl_xor_sync(0xffffffffu, ps, off);
            if (lane == 0) {
                float corr = __expf(oldm - newm);
                sm.rowcorr[r] = corr;
                sm.rowsum[r]  = sm.rowsum[r] * corr + ps;
                sm.rowmax[r]  = newm;
            }
        }
        __syncthreads();

        // ----- PV (3xTF32): warp computes 32x32 of the 64x128 output
        #pragma unroll
        for (int mt = 0; mt < 2; mt++) {
            int r = wmP * 32 + mt * 16 + g;
            float c0 = sm.rowcorr[r], c1 = sm.rowcorr[r + 8];
            #pragma unroll
            for (int nt = 0; nt < 4; nt++) {
                pv[mt][nt][0] *= c0; pv[mt][nt][1] *= c0;
                pv[mt][nt][2] *= c1; pv[mt][nt][3] *= c1;
            }
        }
        #pragma unroll 4
        for (int ks = 0; ks < 8; ks++) {
            const int kk = ks * 8;
            unsigned ah[2][4], al[2][4];
            #pragma unroll
            for (int mt = 0; mt < 2; mt++) {
                int m0 = wmP * 32 + mt * 16;
                split_tf32(sm.P[m0 + g    ][kk + tig    ], ah[mt][0], al[mt][0]);
                split_tf32(sm.P[m0 + g + 8][kk + tig    ], ah[mt][1], al[mt][1]);
                split_tf32(sm.P[m0 + g    ][kk + tig + 4], ah[mt][2], al[mt][2]);
                split_tf32(sm.P[m0 + g + 8][kk + tig + 4], ah[mt][3], al[mt][3]);
            }
            #pragma unroll
            for (int nt = 0; nt < 4; nt++) {
                int nc = wnP * 32 + nt * 8 + g;
                unsigned bh0, bl0, bh1, bl1;
                split_tf32(sm.Vs[kk + tig    ][nc], bh0, bl0);
                split_tf32(sm.Vs[kk + tig + 4][nc], bh1, bl1);
                #pragma unroll
                for (int mt = 0; mt < 2; mt++) {
                    mma_tf32(pv[mt][nt], ah[mt][0], ah[mt][1], ah[mt][2], ah[mt][3], bl0, bl1);
                    mma_tf32(pv[mt][nt], al[mt][0], al[mt][1], al[mt][2], al[mt][3], bh0, bh1);
                    mma_tf32(pv[mt][nt], ah[mt][0], ah[mt][1], ah[mt][2], ah[mt][3], bh0, bh1);
                }
            }
        }
    }
    __syncthreads();

    // epilogue: normalize, write [b, s, h*d]
    #pragma unroll
    for (int mt = 0; mt < 2; mt++) {
        int r = wmP * 32 + mt * 16 + g;
        float inv0 = 1.0f / sm.rowsum[r];
        float inv1 = 1.0f / sm.rowsum[r + 8];
        #pragma unroll
        for (int nt = 0; nt < 4; nt++) {
            int col = wnP * 32 + nt * 8 + tig * 2;
            float* d0 = g_attn + ((size_t)b * Sq + qt * 64 + r) * HID + h * Dd + col;
            float* d1 = g_attn + ((size_t)b * Sq + qt * 64 + r + 8) * HID + h * Dd + col;
            *(float2*)d0 = make_float2(pv[mt][nt][0] * inv0, pv[mt][nt][1] * inv0);
            *(float2*)d1 = make_float2(pv[mt][nt][2] * inv1, pv[mt][nt][3] * inv1);
        }
    }
}

// ---------------------------------------------------------------------------
// KV cache broadcast: key/value outputs replicate k/v over 16 heads.
// ---------------------------------------------------------------------------
__global__ __launch_bounds__(256)
void kv_broadcast(float* __restrict__ out)
{
    int i = blockIdx.x * 256 + threadIdx.x;   // float4 index, 131072 total
    int o = i * 4;
    int b = o / (Sq * Dd);
    int rem = o - b * Sq * Dd;
    int s = rem / Dd;
    int d = rem - s * Dd;
    float4 kv = *(const float4*)&g_k[o];
    float4 vv = *(const float4*)&g_v[o];
    const size_t keybase = (size_t)MM * HID;                       // 8388608
    const size_t valbase = keybase + (size_t)Bz * Hh * Sq * Dd;    // 16777216
    #pragma unroll
    for (int h = 0; h < Hh; h++) {
        size_t idx = (((size_t)b * Hh + h) * Sq + s) * Dd + d;
        *(float4*)&out[keybase + idx] = kv;
        *(float4*)&out[valbase + idx] = vv;
    }
}

// ---------------------------------------------------------------------------
extern "C" void kernel_launch(void* const* d_in, const int* in_sizes, int n_in,
                              void* d_out, int out_size)
{
    const float* hs   = (const float*)d_in[0];
    const float* mask = (const float*)d_in[1];
    const float* Wq   = (const float*)d_in[2];
    const float* Wk   = (const float*)d_in[3];
    const float* Wv   = (const float*)d_in[4];
    const float* Wo   = (const float*)d_in[5];
    float* out = (float*)d_out;

    void *pq, *pk, *pv, *pa;
    cudaGetSymbolAddress(&pq, g_q);
    cudaGetSymbolAddress(&pk, g_k);
    cudaGetSymbolAddress(&pv, g_v);
    cudaGetSymbolAddress(&pa, g_attn);

    cudaFuncSetAttribute(attn_kernel, cudaFuncAttributeMaxDynamicSharedMemorySize,
                         (int)sizeof(AttnSmem));

    dim3 blk(256);
    // Q projection: [4096,2048] = hs @ Wq^T
    gemm_tf32x3<<<dim3(HID / BN, MM / BM), blk>>>(hs, Wq, (float*)pq, MM, HID, HID);
    // K / V projections: [4096,128]
    gemm_tf32x3<<<dim3(Dd / BN, MM / BM), blk>>>(hs, Wk, (float*)pk, MM, Dd, HID);
    gemm_tf32x3<<<dim3(Dd / BN, MM / BM), blk>>>(hs, Wv, (float*)pv, MM, Dd, HID);
    // KV cache broadcast outputs
    kv_broadcast<<<(MM * Dd / 4 + 255) / 256, blk>>>(out);
    // fused attention
    attn_kernel<<<dim3(Sq / 64, Bz * Hh), blk, sizeof(AttnSmem)>>>(mask);
    // output projection -> out[0 : 8388608]
    gemm_tf32x3<<<dim3(HID / BN, MM / BM), blk>>>((const float*)pa, Wo, out, MM, HID, HID);
}

// round 5
// speedup vs baseline: 2.3435x; 1.6290x over previous
#include <cuda_runtime.h>
#include <cuda_bf16.h>
#include <math.h>

#define Bz   2
#define Sq   2048
#define Hh   16
#define Dd   128
#define HID  2048
#define MM   (Bz*Sq)        // 4096

// ---------------- scratch (static device globals; no allocs) ----------------
__device__ float g_q[MM*HID];     // Q projection  [b*s, h*d]
__device__ float g_k[MM*Dd];      // K projection  [b*s, d]
__device__ float g_v[MM*Dd];      // V projection  [b*s, d]  (natural, for cache out)
__device__ float g_vT[Dd*MM];     // V projection transposed [d, b*s] (for PV B-operand)
__device__ float g_attn[MM*HID];  // attn output   [b*s, h*d]

// ---------------------------------------------------------------------------
// helpers: bf16 hi/lo split (packed x2) + bf16 mma
// ---------------------------------------------------------------------------
__device__ __forceinline__ void split2(float x0, float x1, unsigned& hi, unsigned& lo)
{
    __nv_bfloat16 h0 = __float2bfloat16(x0);
    __nv_bfloat16 h1 = __float2bfloat16(x1);
    __nv_bfloat16 l0 = __float2bfloat16(x0 - __bfloat162float(h0));
    __nv_bfloat16 l1 = __float2bfloat16(x1 - __bfloat162float(h1));
    hi = ((unsigned)__bfloat16_as_ushort(h1) << 16) | (unsigned)__bfloat16_as_ushort(h0);
    lo = ((unsigned)__bfloat16_as_ushort(l1) << 16) | (unsigned)__bfloat16_as_ushort(l0);
}

__device__ __forceinline__ void mma_bf16(float c[4],
    unsigned a0, unsigned a1, unsigned a2, unsigned a3,
    unsigned b0, unsigned b1)
{
    asm volatile(
        "mma.sync.aligned.m16n8k16.row.col.f32.bf16.bf16.f32 "
        "{%0,%1,%2,%3}, {%4,%5,%6,%7}, {%8,%9}, {%0,%1,%2,%3};"
        : "+f"(c[0]), "+f"(c[1]), "+f"(c[2]), "+f"(c[3])
        : "r"(a0), "r"(a1), "r"(a2), "r"(a3), "r"(b0), "r"(b1));
}

// ---------------------------------------------------------------------------
// 3xBF16 GEMM body:  C[M,N] = A[M,K] @ W[N,K]^T   (optionally also CT[N,M])
// 128x128 block, BK=32, 256 threads (8 warps 4x2), warp tile 32m x 64n.
// smem: packed bf16x2 words, 16 data words + 4 pad per row (stride 20).
// ---------------------------------------------------------------------------
#define BM 128
#define BN 128
#define BK 32
#define WS 20    // u32 words per row; 20 % 32 == 4·? -> bank = (20r+tig)%32 bijective over (r%8, tig)

__device__ __forceinline__ void gemm_body(
    const float* __restrict__ A, const float* __restrict__ W,
    float* __restrict__ C, float* __restrict__ CT,
    int M, int N, int K, int bm, int bn,
    unsigned* Ah, unsigned* Al, unsigned* Bh, unsigned* Bl)
{
    const int t    = threadIdx.x;
    const int lane = t & 31, w = t >> 5;
    const int g    = lane >> 2, tig = lane & 3;
    const int wm   = w >> 1;        // 0..3
    const int wn   = w & 1;         // 0..1

    float acc[2][8][4];
    #pragma unroll
    for (int i = 0; i < 2; i++)
        #pragma unroll
        for (int j = 0; j < 8; j++)
            #pragma unroll
            for (int q = 0; q < 4; q++) acc[i][j][q] = 0.f;

    // prefetch tile 0
    float4 pa[4], pb[4];
    #pragma unroll
    for (int i = 0; i < 4; i++) {
        int f = t + 256 * i;
        int r = f >> 3, kc = (f & 7) * 4;
        pa[i] = *(const float4*)&A[(size_t)(bm + r) * K + kc];
        pb[i] = *(const float4*)&W[(size_t)(bn + r) * K + kc];
    }

    for (int k0 = 0; k0 < K; k0 += BK) {
        // store prefetched tile (split once)
        #pragma unroll
        for (int i = 0; i < 4; i++) {
            int f = t + 256 * i;
            int r = f >> 3, kc = (f & 7) * 4;
            unsigned h0, l0, h1, l1;
            split2(pa[i].x, pa[i].y, h0, l0);
            split2(pa[i].z, pa[i].w, h1, l1);
            Ah[r * WS + kc / 2] = h0; Ah[r * WS + kc / 2 + 1] = h1;
            Al[r * WS + kc / 2] = l0; Al[r * WS + kc / 2 + 1] = l1;
            split2(pb[i].x, pb[i].y, h0, l0);
            split2(pb[i].z, pb[i].w, h1, l1);
            Bh[r * WS + kc / 2] = h0; Bh[r * WS + kc / 2 + 1] = h1;
            Bl[r * WS + kc / 2] = l0; Bl[r * WS + kc / 2 + 1] = l1;
        }
        __syncthreads();

        if (k0 + BK < K) {
            #pragma unroll
            for (int i = 0; i < 4; i++) {
                int f = t + 256 * i;
                int r = f >> 3, kc = (f & 7) * 4;
                pa[i] = *(const float4*)&A[(size_t)(bm + r) * K + k0 + BK + kc];
                pb[i] = *(const float4*)&W[(size_t)(bn + r) * K + k0 + BK + kc];
            }
        }

        #pragma unroll
        for (int ks = 0; ks < 2; ks++) {
            const int kw = ks * 8;
            unsigned ah[2][4], al[2][4];
            #pragma unroll
            for (int mt = 0; mt < 2; mt++) {
                int m0 = wm * 32 + mt * 16;
                ah[mt][0] = Ah[(m0 + g    ) * WS + kw + tig];
                ah[mt][1] = Ah[(m0 + g + 8) * WS + kw + tig];
                ah[mt][2] = Ah[(m0 + g    ) * WS + kw + 4 + tig];
                ah[mt][3] = Ah[(m0 + g + 8) * WS + kw + 4 + tig];
                al[mt][0] = Al[(m0 + g    ) * WS + kw + tig];
                al[mt][1] = Al[(m0 + g + 8) * WS + kw + tig];
                al[mt][2] = Al[(m0 + g    ) * WS + kw + 4 + tig];
                al[mt][3] = Al[(m0 + g + 8) * WS + kw + 4 + tig];
            }
            #pragma unroll
            for (int nt = 0; nt < 8; nt++) {
                int nc = wn * 64 + nt * 8 + g;
                unsigned bh0 = Bh[nc * WS + kw + tig];
                unsigned bh1 = Bh[nc * WS + kw + 4 + tig];
                unsigned bl0 = Bl[nc * WS + kw + tig];
                unsigned bl1 = Bl[nc * WS + kw + 4 + tig];
                #pragma unroll
                for (int mt = 0; mt < 2; mt++) {
                    mma_bf16(acc[mt][nt], ah[mt][0], ah[mt][1], ah[mt][2], ah[mt][3], bl0, bl1);
                    mma_bf16(acc[mt][nt], al[mt][0], al[mt][1], al[mt][2], al[mt][3], bh0, bh1);
                    mma_bf16(acc[mt][nt], ah[mt][0], ah[mt][1], ah[mt][2], ah[mt][3], bh0, bh1);
                }
            }
        }
        __syncthreads();
    }

    // epilogue
    #pragma unroll
    for (int mt = 0; mt < 2; mt++) {
        int r0 = bm + wm * 32 + mt * 16 + g;
        #pragma unroll
        for (int nt = 0; nt < 8; nt++) {
            int c0 = bn + wn * 64 + nt * 8 + tig * 2;
            *(float2*)&C[(size_t)r0 * N + c0]       = make_float2(acc[mt][nt][0], acc[mt][nt][1]);
            *(float2*)&C[(size_t)(r0 + 8) * N + c0] = make_float2(acc[mt][nt][2], acc[mt][nt][3]);
            if (CT) {
                CT[(size_t)c0 * M + r0]           = acc[mt][nt][0];
                CT[(size_t)(c0 + 1) * M + r0]     = acc[mt][nt][1];
                CT[(size_t)c0 * M + r0 + 8]       = acc[mt][nt][2];
                CT[(size_t)(c0 + 1) * M + r0 + 8] = acc[mt][nt][3];
            }
        }
    }
}

__global__ __launch_bounds__(256)
void gemm_bf16x3(const float* __restrict__ A, const float* __restrict__ W,
                 float* __restrict__ C, int M, int N, int K)
{
    __shared__ unsigned Ah[BM * WS], Al[BM * WS], Bh[BN * WS], Bl[BN * WS];
    gemm_body(A, W, C, nullptr, M, N, K, blockIdx.y * BM, blockIdx.x * BN,
              Ah, Al, Bh, Bl);
}

// K and V projections in one launch; z=1 (V) also writes transposed copy.
__global__ __launch_bounds__(256)
void gemm_kv(const float* __restrict__ A,
             const float* __restrict__ Wk, const float* __restrict__ Wv,
             float* __restrict__ Ck, float* __restrict__ Cv, float* __restrict__ CvT,
             int M, int N, int K)
{
    __shared__ unsigned Ah[BM * WS], Al[BM * WS], Bh[BN * WS], Bl[BN * WS];
    const float* W = blockIdx.z ? Wv : Wk;
    float* C  = blockIdx.z ? Cv  : Ck;
    float* CT = blockIdx.z ? CvT : nullptr;
    gemm_body(A, W, C, CT, M, N, K, blockIdx.y * BM, blockIdx.x * BN,
              Ah, Al, Bh, Bl);
}

// ---------------------------------------------------------------------------
// Flash attention with 3xBF16 mma. Block = 64 q rows of one (b,h).
// All operands pre-split to packed bf16x2 hi/lo words in smem.
// Word strides: Q/K rows 68 (64 data + 4 pad), V/P rows 36 (32 data + 4 pad)
// -> fragment LDS bank = (4*row + tig) mod 32 : conflict-free.
// ---------------------------------------------------------------------------
struct AttnSmem {
    unsigned Qh[64*68], Ql[64*68];
    unsigned Kh[64*68], Kl[64*68];
    unsigned Vh[128*36], Vl[128*36];   // V^T: [d][k] pairs along k
    float    S [64*68];
    unsigned Ph[64*36], Pl[64*36];     // probs [q][k]
    float maskv[64];
    float rowmax[64];
    float rowsum[64];
    float rowcorr[64];
};

__global__ __launch_bounds__(256)
void attn_kernel(const float* __restrict__ mask)
{
    extern __shared__ char smem_raw[];
    AttnSmem& sm = *reinterpret_cast<AttnSmem*>(smem_raw);

    const int t    = threadIdx.x;
    const int lane = t & 31, w = t >> 5;
    const int g    = lane >> 2, tig = lane & 3;
    const int qt   = blockIdx.x;           // 0..31
    const int bh   = blockIdx.y;           // 0..31
    const int b    = bh / Hh;
    const int h    = bh % Hh;

    const int wmQ = w >> 1, wnQ = w & 1;   // QK: 4x2 warps, tile 16m x 32n
    const int wmP = w >> 2, wnP = w & 3;   // PV: 2x4 warps, tile 32m x 32n

    const float* qptr  = g_q  + (size_t)b * Sq * HID + h * Dd;
    const float* kptr  = g_k  + (size_t)b * Sq * Dd;
    const float* vTptr = g_vT + (size_t)b * Sq;     // + d*MM + (kt*64 + kc)

    // load + split Q tile [64][128]
    #pragma unroll
    for (int j = 0; j < 8; j++) {
        int f = t + 256 * j;
        int r = f >> 5, dc = (f & 31) * 4;
        float4 q4 = *(const float4*)(qptr + (size_t)(qt * 64 + r) * HID + dc);
        unsigned h0, l0, h1, l1;
        split2(q4.x, q4.y, h0, l0);
        split2(q4.z, q4.w, h1, l1);
        sm.Qh[r * 68 + dc / 2] = h0; sm.Qh[r * 68 + dc / 2 + 1] = h1;
        sm.Ql[r * 68 + dc / 2] = l0; sm.Ql[r * 68 + dc / 2 + 1] = l1;
    }
    if (t < 64) { sm.rowmax[t] = -INFINITY; sm.rowsum[t] = 0.f; }

    float pv[2][4][4];
    #pragma unroll
    for (int i = 0; i < 2; i++)
        #pragma unroll
        for (int j = 0; j < 4; j++)
            #pragma unroll
            for (int q = 0; q < 4; q++) pv[i][j][q] = 0.f;

    const float scale = 0.08838834764831845f;   // 1/sqrt(128)
    const float NEG   = -3.402823466e38f;

    for (int kt = 0; kt < Sq / 64; kt++) {
        __syncthreads();   // prior iteration's reads done before overwrite

        // K tile [64 rows][128 d]
        #pragma unroll
        for (int j = 0; j < 8; j++) {
            int f = t + 256 * j;
            int r = f >> 5, dc = (f & 31) * 4;
            float4 k4 = *(const float4*)(kptr + (size_t)(kt * 64 + r) * Dd + dc);
            unsigned h0, l0, h1, l1;
            split2(k4.x, k4.y, h0, l0);
            split2(k4.z, k4.w, h1, l1);
            sm.Kh[r * 68 + dc / 2] = h0; sm.Kh[r * 68 + dc / 2 + 1] = h1;
            sm.Kl[r * 68 + dc / 2] = l0; sm.Kl[r * 68 + dc / 2 + 1] = l1;
        }
        // V tile from transposed layout: [d 128][k 64]
        #pragma unroll
        for (int j = 0; j < 8; j++) {
            int f = t + 256 * j;
            int n = f >> 4, kc = (f & 15) * 4;
            float4 v4 = *(const float4*)(vTptr + (size_t)n * MM + kt * 64 + kc);
            unsigned h0, l0, h1, l1;
            split2(v4.x, v4.y, h0, l0);
            split2(v4.z, v4.w, h1, l1);
            sm.Vh[n * 36 + kc / 2] = h0; sm.Vh[n * 36 + kc / 2 + 1] = h1;
            sm.Vl[n * 36 + kc / 2] = l0; sm.Vl[n * 36 + kc / 2 + 1] = l1;
        }
        if (t < 64) sm.maskv[t] = mask[b * Sq + kt * 64 + t];
        __syncthreads();

        // ----- QK^T : warp computes 16x32 of 64x64 score tile
        float cqk[4][4];
        #pragma unroll
        for (int nt = 0; nt < 4; nt++)
            #pragma unroll
            for (int q = 0; q < 4; q++) cqk[nt][q] = 0.f;

        #pragma unroll
        for (int ks = 0; ks < 8; ks++) {
            const int kw = ks * 8;
            const int m0 = wmQ * 16;
            unsigned ah0 = sm.Qh[(m0 + g    ) * 68 + kw + tig];
            unsigned ah1 = sm.Qh[(m0 + g + 8) * 68 + kw + tig];
            unsigned ah2 = sm.Qh[(m0 + g    ) * 68 + kw + 4 + tig];
            unsigned ah3 = sm.Qh[(m0 + g + 8) * 68 + kw + 4 + tig];
            unsigned al0 = sm.Ql[(m0 + g    ) * 68 + kw + tig];
            unsigned al1 = sm.Ql[(m0 + g + 8) * 68 + kw + tig];
            unsigned al2 = sm.Ql[(m0 + g    ) * 68 + kw + 4 + tig];
            unsigned al3 = sm.Ql[(m0 + g + 8) * 68 + kw + 4 + tig];
            #pragma unroll
            for (int nt = 0; nt < 4; nt++) {
                int nc = wnQ * 32 + nt * 8 + g;
                unsigned bh0 = sm.Kh[nc * 68 + kw + tig];
                unsigned bh1 = sm.Kh[nc * 68 + kw + 4 + tig];
                unsigned bl0 = sm.Kl[nc * 68 + kw + tig];
                unsigned bl1 = sm.Kl[nc * 68 + kw + 4 + tig];
                mma_bf16(cqk[nt], ah0, ah1, ah2, ah3, bl0, bl1);
                mma_bf16(cqk[nt], al0, al1, al2, al3, bh0, bh1);
                mma_bf16(cqk[nt], ah0, ah1, ah2, ah3, bh0, bh1);
            }
        }
        #pragma unroll
        for (int nt = 0; nt < 4; nt++) {
            int col = wnQ * 32 + nt * 8 + tig * 2;
            int row = wmQ * 16 + g;
            float mt0 = (1.0f - sm.maskv[col])     * NEG;
            float mt1 = (1.0f - sm.maskv[col + 1]) * NEG;
            sm.S[ row      * 68 + col    ] = cqk[nt][0] * scale + mt0;
            sm.S[ row      * 68 + col + 1] = cqk[nt][1] * scale + mt1;
            sm.S[(row + 8) * 68 + col    ] = cqk[nt][2] * scale + mt0;
            sm.S[(row + 8) * 68 + col + 1] = cqk[nt][3] * scale + mt1;
        }
        __syncthreads();

        // ----- online softmax: warp w owns rows w*8..w*8+7; lane owns col pair
        #pragma unroll
        for (int rr = 0; rr < 8; rr++) {
            int r = w * 8 + rr;
            float s0 = sm.S[r * 68 + 2 * lane];
            float s1 = sm.S[r * 68 + 2 * lane + 1];
            float m = fmaxf(s0, s1);
            #pragma unroll
            for (int off = 16; off; off >>= 1)
                m = fmaxf(m, __shfl_xor_sync(0xffffffffu, m, off));
            float oldm = sm.rowmax[r];
            float newm = fmaxf(oldm, m);
            float p0 = __expf(s0 - newm), p1 = __expf(s1 - newm);
            unsigned ph, pl;
            split2(p0, p1, ph, pl);
            sm.Ph[r * 36 + lane] = ph;
            sm.Pl[r * 36 + lane] = pl;
            float ps = p0 + p1;
            #pragma unroll
            for (int off = 16; off; off >>= 1)
                ps += __shfl_xor_sync(0xffffffffu, ps, off);
            if (lane == 0) {
                float corr = __expf(oldm - newm);
                sm.rowcorr[r] = corr;
                sm.rowsum[r]  = sm.rowsum[r] * corr + ps;
                sm.rowmax[r]  = newm;
            }
        }
        __syncthreads();

        // ----- PV : warp computes 32x32 of 64x128 output
        #pragma unroll
        for (int mt = 0; mt < 2; mt++) {
            int r = wmP * 32 + mt * 16 + g;
            float c0 = sm.rowcorr[r], c1 = sm.rowcorr[r + 8];
            #pragma unroll
            for (int nt = 0; nt < 4; nt++) {
                pv[mt][nt][0] *= c0; pv[mt][nt][1] *= c0;
                pv[mt][nt][2] *= c1; pv[mt][nt][3] *= c1;
            }
        }
        #pragma unroll
        for (int ks = 0; ks < 4; ks++) {
            const int kw = ks * 8;
            unsigned ah[2][4], al[2][4];
            #pragma unroll
            for (int mt = 0; mt < 2; mt++) {
                int m0 = wmP * 32 + mt * 16;
                ah[mt][0] = sm.Ph[(m0 + g    ) * 36 + kw + tig];
                ah[mt][1] = sm.Ph[(m0 + g + 8) * 36 + kw + tig];
                ah[mt][2] = sm.Ph[(m0 + g    ) * 36 + kw + 4 + tig];
                ah[mt][3] = sm.Ph[(m0 + g + 8) * 36 + kw + 4 + tig];
                al[mt][0] = sm.Pl[(m0 + g    ) * 36 + kw + tig];
                al[mt][1] = sm.Pl[(m0 + g + 8) * 36 + kw + tig];
                al[mt][2] = sm.Pl[(m0 + g    ) * 36 + kw + 4 + tig];
                al[mt][3] = sm.Pl[(m0 + g + 8) * 36 + kw + 4 + tig];
            }
            #pragma unroll
            for (int nt = 0; nt < 4; nt++) {
                int nc = wnP * 32 + nt * 8 + g;
                unsigned bh0 = sm.Vh[nc * 36 + kw + tig];
                unsigned bh1 = sm.Vh[nc * 36 + kw + 4 + tig];
                unsigned bl0 = sm.Vl[nc * 36 + kw + tig];
                unsigned bl1 = sm.Vl[nc * 36 + kw + 4 + tig];
                #pragma unroll
                for (int mt = 0; mt < 2; mt++) {
                    mma_bf16(pv[mt][nt], ah[mt][0], ah[mt][1], ah[mt][2], ah[mt][3], bl0, bl1);
                    mma_bf16(pv[mt][nt], al[mt][0], al[mt][1], al[mt][2], al[mt][3], bh0, bh1);
                    mma_bf16(pv[mt][nt], ah[mt][0], ah[mt][1], ah[mt][2], ah[mt][3], bh0, bh1);
                }
            }
        }
    }
    __syncthreads();

    // epilogue: normalize, write [b, s, h*d]
    #pragma unroll
    for (int mt = 0; mt < 2; mt++) {
        int r = wmP * 32 + mt * 16 + g;
        float inv0 = 1.0f / sm.rowsum[r];
        float inv1 = 1.0f / sm.rowsum[r + 8];
        #pragma unroll
        for (int nt = 0; nt < 4; nt++) {
            int col = wnP * 32 + nt * 8 + tig * 2;
            float* d0 = g_attn + ((size_t)b * Sq + qt * 64 + r) * HID + h * Dd + col;
            float* d1 = g_attn + ((size_t)b * Sq + qt * 64 + r + 8) * HID + h * Dd + col;
            *(float2*)d0 = make_float2(pv[mt][nt][0] * inv0, pv[mt][nt][1] * inv0);
            *(float2*)d1 = make_float2(pv[mt][nt][2] * inv1, pv[mt][nt][3] * inv1);
        }
    }
}

// ---------------------------------------------------------------------------
// KV cache broadcast: key/value outputs replicate k/v over 16 heads.
// ---------------------------------------------------------------------------
__global__ __launch_bounds__(256)
void kv_broadcast(float* __restrict__ out)
{
    int i = blockIdx.x * 256 + threadIdx.x;   // float4 index, 131072 total
    int o = i * 4;
    int b = o / (Sq * Dd);
    int rem = o - b * Sq * Dd;
    int s = rem / Dd;
    int d = rem - s * Dd;
    float4 kv = *(const float4*)&g_k[o];
    float4 vv = *(const float4*)&g_v[o];
    const size_t keybase = (size_t)MM * HID;                       // 8388608
    const size_t valbase = keybase + (size_t)Bz * Hh * Sq * Dd;    // 16777216
    #pragma unroll
    for (int h = 0; h < Hh; h++) {
        size_t idx = (((size_t)b * Hh + h) * Sq + s) * Dd + d;
        *(float4*)&out[keybase + idx] = kv;
        *(float4*)&out[valbase + idx] = vv;
    }
}

// ---------------------------------------------------------------------------
extern "C" void kernel_launch(void* const* d_in, const int* in_sizes, int n_in,
                              void* d_out, int out_size)
{
    const float* hs   = (const float*)d_in[0];
    const float* mask = (const float*)d_in[1];
    const float* Wq   = (const float*)d_in[2];
    const float* Wk   = (const float*)d_in[3];
    const float* Wv   = (const float*)d_in[4];
    const float* Wo   = (const float*)d_in[5];
    float* out = (float*)d_out;

    void *pq, *pk, *pv, *pvT, *pa;
    cudaGetSymbolAddress(&pq,  g_q);
    cudaGetSymbolAddress(&pk,  g_k);
    cudaGetSymbolAddress(&pv,  g_v);
    cudaGetSymbolAddress(&pvT, g_vT);
    cudaGetSymbolAddress(&pa,  g_attn);

    cudaFuncSetAttribute(attn_kernel, cudaFuncAttributeMaxDynamicSharedMemorySize,
                         (int)sizeof(AttnSmem));

    dim3 blk(256);
    // Q projection: [4096,2048]
    gemm_bf16x3<<<dim3(HID / BN, MM / BM), blk>>>(hs, Wq, (float*)pq, MM, HID, HID);
    // K + V projections fused (z=0 -> K, z=1 -> V natural + transposed)
    gemm_kv<<<dim3(Dd / BN, MM / BM, 2), blk>>>(hs, Wk, Wv,
                                                (float*)pk, (float*)pv, (float*)pvT,
                                                MM, Dd, HID);
    // KV cache broadcast outputs
    kv_broadcast<<<(MM * Dd / 4 + 255) / 256, blk>>>(out);
    // fused attention
    attn_kernel<<<dim3(Sq / 64, Bz * Hh), blk, sizeof(AttnSmem)>>>(mask);
    // output projection -> out[0 : 8388608]
    gemm_bf16x3<<<dim3(HID / BN, MM / BM), blk>>>((const float*)pa, Wo, out, MM, HID, HID);
}

// round 6
// speedup vs baseline: 3.2492x; 1.3865x over previous
#include <cuda_runtime.h>
#include <cuda_bf16.h>
#include <math.h>

#define Bz   2
#define Sq   2048
#define Hh   16
#define Dd   128
#define HID  2048
#define MM   (Bz*Sq)        // 4096

// ---------------- scratch (static device globals; no allocs) ----------------
__device__ unsigned g_q_hi[MM*(HID/2)];   // Q proj, packed bf16x2 hi  [s][hd word]
__device__ unsigned g_q_lo[MM*(HID/2)];
__device__ float    g_k[MM*Dd];           // K proj fp32 (for cache broadcast)
__device__ unsigned g_k_hi[MM*(Dd/2)];    // K packed hi  [s][d word]
__device__ unsigned g_k_lo[MM*(Dd/2)];
__device__ float    g_v[MM*Dd];           // V proj fp32 (for cache broadcast)
__device__ __nv_bfloat16 g_vT_hi[Dd*MM];  // V^T bf16 hi  [d][s]
__device__ __nv_bfloat16 g_vT_lo[Dd*MM];
__device__ unsigned g_a_hi[MM*(HID/2)];   // attn out, packed hi [s][hd word]
__device__ unsigned g_a_lo[MM*(HID/2)];

// ---------------------------------------------------------------------------
// helpers
// ---------------------------------------------------------------------------
__device__ __forceinline__ void split2(float x0, float x1, unsigned& hi, unsigned& lo)
{
    __nv_bfloat16 h0 = __float2bfloat16(x0);
    __nv_bfloat16 h1 = __float2bfloat16(x1);
    __nv_bfloat16 l0 = __float2bfloat16(x0 - __bfloat162float(h0));
    __nv_bfloat16 l1 = __float2bfloat16(x1 - __bfloat162float(h1));
    hi = ((unsigned)__bfloat16_as_ushort(h1) << 16) | (unsigned)__bfloat16_as_ushort(h0);
    lo = ((unsigned)__bfloat16_as_ushort(l1) << 16) | (unsigned)__bfloat16_as_ushort(l0);
}

__device__ __forceinline__ void mma_bf16(float c[4],
    unsigned a0, unsigned a1, unsigned a2, unsigned a3,
    unsigned b0, unsigned b1)
{
    asm volatile(
        "mma.sync.aligned.m16n8k16.row.col.f32.bf16.bf16.f32 "
        "{%0,%1,%2,%3}, {%4,%5,%6,%7}, {%8,%9}, {%0,%1,%2,%3};"
        : "+f"(c[0]), "+f"(c[1]), "+f"(c[2]), "+f"(c[3])
        : "r"(a0), "r"(a1), "r"(a2), "r"(a3), "r"(b0), "r"(b1));
}

__device__ __forceinline__ void cp16(unsigned dst, const void* src)
{
    asm volatile("cp.async.cg.shared.global [%0], [%1], 16;" :: "r"(dst), "l"(src));
}
__device__ __forceinline__ void cp_commit()
{
    asm volatile("cp.async.commit_group;");
}
template<int N>
__device__ __forceinline__ void cp_wait()
{
    asm volatile("cp.async.wait_group %0;" :: "n"(N));
}

// ---------------------------------------------------------------------------
// 3xBF16 GEMM core:  C[M,N] = A[M,K] @ W[N,K]^T
// 128x128 block, BK=32, 256 threads (8 warps 4x2), warp tile 32m x 64n.
// PRESPLIT=1: A given as packed hi/lo words (no in-kernel A split).
// ---------------------------------------------------------------------------
#define BM 128
#define BN 128
#define BK 32
#define WS 20    // u32 words per smem row (16 data + 4 pad)

template<int PRESPLIT>
__device__ __forceinline__ void gemm_core(
    const float* __restrict__ A,
    const unsigned* __restrict__ Ahi, const unsigned* __restrict__ Alo,
    const float* __restrict__ W,
    int M, int N, int K, int bm, int bn,
    unsigned* sAh, unsigned* sAl, unsigned* sBh, unsigned* sBl,
    float acc[2][8][4])
{
    const int t    = threadIdx.x;
    const int lane = t & 31, w = t >> 5;
    const int g    = lane >> 2, tig = lane & 3;
    const int wm   = w >> 1;        // 0..3
    const int wn   = w & 1;         // 0..1
    const int KW   = K >> 1;

    #pragma unroll
    for (int i = 0; i < 2; i++)
        #pragma unroll
        for (int j = 0; j < 8; j++)
            #pragma unroll
            for (int q = 0; q < 4; q++) acc[i][j][q] = 0.f;

    // prefetch tile 0
    float4 pa[4], pb[4];
    uint4 ph[2], pl[2];
    const int rs = t >> 1, wsh = (t & 1) * 8;    // presplit-A mapping
    #pragma unroll
    for (int i = 0; i < 4; i++) {
        int f = t + 256 * i;
        int r = f >> 3, kc = (f & 7) * 4;
        if (!PRESPLIT)
            pa[i] = *(const float4*)&A[(size_t)(bm + r) * K + kc];
        pb[i] = *(const float4*)&W[(size_t)(bn + r) * K + kc];
    }
    if (PRESPLIT) {
        ph[0] = *(const uint4*)&Ahi[(size_t)(bm + rs) * KW + wsh];
        ph[1] = *(const uint4*)&Ahi[(size_t)(bm + rs) * KW + wsh + 4];
        pl[0] = *(const uint4*)&Alo[(size_t)(bm + rs) * KW + wsh];
        pl[1] = *(const uint4*)&Alo[(size_t)(bm + rs) * KW + wsh + 4];
    }

    for (int k0 = 0; k0 < K; k0 += BK) {
        // store prefetched tile
        if (PRESPLIT) {
            *(uint4*)&sAh[rs * WS + wsh]     = ph[0];
            *(uint4*)&sAh[rs * WS + wsh + 4] = ph[1];
            *(uint4*)&sAl[rs * WS + wsh]     = pl[0];
            *(uint4*)&sAl[rs * WS + wsh + 4] = pl[1];
        }
        #pragma unroll
        for (int i = 0; i < 4; i++) {
            int f = t + 256 * i;
            int r = f >> 3, kc = (f & 7) * 4;
            unsigned h0, l0, h1, l1;
            if (!PRESPLIT) {
                split2(pa[i].x, pa[i].y, h0, l0);
                split2(pa[i].z, pa[i].w, h1, l1);
                sAh[r * WS + kc / 2] = h0; sAh[r * WS + kc / 2 + 1] = h1;
                sAl[r * WS + kc / 2] = l0; sAl[r * WS + kc / 2 + 1] = l1;
            }
            split2(pb[i].x, pb[i].y, h0, l0);
            split2(pb[i].z, pb[i].w, h1, l1);
            sBh[r * WS + kc / 2] = h0; sBh[r * WS + kc / 2 + 1] = h1;
            sBl[r * WS + kc / 2] = l0; sBl[r * WS + kc / 2 + 1] = l1;
        }
        __syncthreads();

        if (k0 + BK < K) {
            #pragma unroll
            for (int i = 0; i < 4; i++) {
                int f = t + 256 * i;
                int r = f >> 3, kc = (f & 7) * 4;
                if (!PRESPLIT)
                    pa[i] = *(const float4*)&A[(size_t)(bm + r) * K + k0 + BK + kc];
                pb[i] = *(const float4*)&W[(size_t)(bn + r) * K + k0 + BK + kc];
            }
            if (PRESPLIT) {
                int kw0 = (k0 + BK) >> 1;
                ph[0] = *(const uint4*)&Ahi[(size_t)(bm + rs) * KW + kw0 + wsh];
                ph[1] = *(const uint4*)&Ahi[(size_t)(bm + rs) * KW + kw0 + wsh + 4];
                pl[0] = *(const uint4*)&Alo[(size_t)(bm + rs) * KW + kw0 + wsh];
                pl[1] = *(const uint4*)&Alo[(size_t)(bm + rs) * KW + kw0 + wsh + 4];
            }
        }

        #pragma unroll
        for (int ks = 0; ks < 2; ks++) {
            const int kw = ks * 8;
            unsigned ah[2][4], al[2][4];
            #pragma unroll
            for (int mt = 0; mt < 2; mt++) {
                int m0 = wm * 32 + mt * 16;
                ah[mt][0] = sAh[(m0 + g    ) * WS + kw + tig];
                ah[mt][1] = sAh[(m0 + g + 8) * WS + kw + tig];
                ah[mt][2] = sAh[(m0 + g    ) * WS + kw + 4 + tig];
                ah[mt][3] = sAh[(m0 + g + 8) * WS + kw + 4 + tig];
                al[mt][0] = sAl[(m0 + g    ) * WS + kw + tig];
                al[mt][1] = sAl[(m0 + g + 8) * WS + kw + tig];
                al[mt][2] = sAl[(m0 + g    ) * WS + kw + 4 + tig];
                al[mt][3] = sAl[(m0 + g + 8) * WS + kw + 4 + tig];
            }
            #pragma unroll
            for (int nt = 0; nt < 8; nt++) {
                int nc = wn * 64 + nt * 8 + g;
                unsigned bh0 = sBh[nc * WS + kw + tig];
                unsigned bh1 = sBh[nc * WS + kw + 4 + tig];
                unsigned bl0 = sBl[nc * WS + kw + tig];
                unsigned bl1 = sBl[nc * WS + kw + 4 + tig];
                #pragma unroll
                for (int mt = 0; mt < 2; mt++) {
                    mma_bf16(acc[mt][nt], ah[mt][0], ah[mt][1], ah[mt][2], ah[mt][3], bl0, bl1);
                    mma_bf16(acc[mt][nt], al[mt][0], al[mt][1], al[mt][2], al[mt][3], bh0, bh1);
                    mma_bf16(acc[mt][nt], ah[mt][0], ah[mt][1], ah[mt][2], ah[mt][3], bh0, bh1);
                }
            }
        }
        __syncthreads();
    }
}

// ---- Q projection: writes packed hi/lo only --------------------------------
__global__ __launch_bounds__(256)
void gemm_q(const float* __restrict__ A, const float* __restrict__ W,
            unsigned* __restrict__ Chi, unsigned* __restrict__ Clo,
            int M, int N, int K)
{
    __shared__ unsigned sAh[BM * WS], sAl[BM * WS], sBh[BN * WS], sBl[BN * WS];
    float acc[2][8][4];
    const int bm = blockIdx.y * BM, bn = blockIdx.x * BN;
    gemm_core<0>(A, nullptr, nullptr, W, M, N, K, bm, bn, sAh, sAl, sBh, sBl, acc);

    const int t = threadIdx.x, lane = t & 31, w = t >> 5;
    const int g = lane >> 2, tig = lane & 3;
    const int wm = w >> 1, wn = w & 1;
    const int NW = N >> 1;
    #pragma unroll
    for (int mt = 0; mt < 2; mt++) {
        int r0 = bm + wm * 32 + mt * 16 + g;
        #pragma unroll
        for (int nt = 0; nt < 8; nt++) {
            int cw = (bn + wn * 64 + nt * 8 + tig * 2) >> 1;
            unsigned h0, l0;
            split2(acc[mt][nt][0], acc[mt][nt][1], h0, l0);
            Chi[(size_t)r0 * NW + cw] = h0;
            Clo[(size_t)r0 * NW + cw] = l0;
            split2(acc[mt][nt][2], acc[mt][nt][3], h0, l0);
            Chi[(size_t)(r0 + 8) * NW + cw] = h0;
            Clo[(size_t)(r0 + 8) * NW + cw] = l0;
        }
    }
}

// ---- K + V projections (z=0 -> K, z=1 -> V) --------------------------------
__global__ __launch_bounds__(256)
void gemm_kv(const float* __restrict__ A,
             const float* __restrict__ Wk, const float* __restrict__ Wv,
             int M, int N, int K)
{
    __shared__ unsigned sAh[BM * WS], sAl[BM * WS], sBh[BN * WS], sBl[BN * WS];
    float acc[2][8][4];
    const int bm = blockIdx.y * BM, bn = blockIdx.x * BN;
    const float* W = blockIdx.z ? Wv : Wk;
    gemm_core<0>(A, nullptr, nullptr, W, M, N, K, bm, bn, sAh, sAl, sBh, sBl, acc);

    const int t = threadIdx.x, lane = t & 31, w = t >> 5;
    const int g = lane >> 2, tig = lane & 3;
    const int wm = w >> 1, wn = w & 1;
    const int NW = N >> 1;
    #pragma unroll
    for (int mt = 0; mt < 2; mt++) {
        int r0 = bm + wm * 32 + mt * 16 + g;
        #pragma unroll
        for (int nt = 0; nt < 8; nt++) {
            int c0 = bn + wn * 64 + nt * 8 + tig * 2;
            float a0 = acc[mt][nt][0], a1 = acc[mt][nt][1];
            float a2 = acc[mt][nt][2], a3 = acc[mt][nt][3];
            if (blockIdx.z == 0) {
                *(float2*)&g_k[(size_t)r0 * N + c0]       = make_float2(a0, a1);
                *(float2*)&g_k[(size_t)(r0 + 8) * N + c0] = make_float2(a2, a3);
                unsigned h0, l0;
                split2(a0, a1, h0, l0);
                g_k_hi[(size_t)r0 * NW + (c0 >> 1)] = h0;
                g_k_lo[(size_t)r0 * NW + (c0 >> 1)] = l0;
                split2(a2, a3, h0, l0);
                g_k_hi[(size_t)(r0 + 8) * NW + (c0 >> 1)] = h0;
                g_k_lo[(size_t)(r0 + 8) * NW + (c0 >> 1)] = l0;
            } else {
                *(float2*)&g_v[(size_t)r0 * N + c0]       = make_float2(a0, a1);
                *(float2*)&g_v[(size_t)(r0 + 8) * N + c0] = make_float2(a2, a3);
                #pragma unroll
                for (int q = 0; q < 4; q++) {
                    float val = acc[mt][nt][q];
                    int cc = c0 + (q & 1);
                    int rr = r0 + (q >> 1) * 8;
                    __nv_bfloat16 hh = __float2bfloat16(val);
                    __nv_bfloat16 ll = __float2bfloat16(val - __bfloat162float(hh));
                    g_vT_hi[(size_t)cc * MM + rr] = hh;
                    g_vT_lo[(size_t)cc * MM + rr] = ll;
                }
            }
        }
    }
}

// ---- O projection: A pre-split, fp32 output --------------------------------
__global__ __launch_bounds__(256)
void gemm_o(const float* __restrict__ W, float* __restrict__ C,
            int M, int N, int K)
{
    __shared__ unsigned sAh[BM * WS], sAl[BM * WS], sBh[BN * WS], sBl[BN * WS];
    float acc[2][8][4];
    const int bm = blockIdx.y * BM, bn = blockIdx.x * BN;
    gemm_core<1>(nullptr, g_a_hi, g_a_lo, W, M, N, K, bm, bn, sAh, sAl, sBh, sBl, acc);

    const int t = threadIdx.x, lane = t & 31, w = t >> 5;
    const int g = lane >> 2, tig = lane & 3;
    const int wm = w >> 1, wn = w & 1;
    #pragma unroll
    for (int mt = 0; mt < 2; mt++) {
        int r0 = bm + wm * 32 + mt * 16 + g;
        #pragma unroll
        for (int nt = 0; nt < 8; nt++) {
            int c0 = bn + wn * 64 + nt * 8 + tig * 2;
            *(float2*)&C[(size_t)r0 * N + c0]       = make_float2(acc[mt][nt][0], acc[mt][nt][1]);
            *(float2*)&C[(size_t)(r0 + 8) * N + c0] = make_float2(acc[mt][nt][2], acc[mt][nt][3]);
        }
    }
}

// ---------------------------------------------------------------------------
// FlashAttention-2 style attention: 128 q rows per block, warp owns 16 rows.
// Register softmax (quad shfl), cp.async double-buffered K/V, Q in registers.
// Smem word layout: K rows stride 68 (64 data + 4 pad), V^T rows stride 36.
// ---------------------------------------------------------------------------
#define KBUF (64*68)
#define VBUF (128*36)
#define ATTN_SMEM_WORDS (4*KBUF + 4*VBUF + Sq)
#define NT_TILES (Sq/64)

__global__ __launch_bounds__(256, 1)
void attn_kernel(const float* __restrict__ mask)
{
    extern __shared__ unsigned smw[];
    unsigned* Kh0 = smw;
    unsigned* Kl0 = smw + 2*KBUF;
    unsigned* Vh0 = smw + 4*KBUF;
    unsigned* Vl0 = smw + 4*KBUF + 2*VBUF;
    float*  maskrow = (float*)(smw + 4*KBUF + 4*VBUF);

    const unsigned sbase = (unsigned)__cvta_generic_to_shared(smw);

    const int t    = threadIdx.x;
    const int lane = t & 31, w = t >> 5;
    const int g    = lane >> 2, tig = lane & 3;
    const int qt   = blockIdx.x;           // 0..15 (128-row q tiles)
    const int bh   = blockIdx.y;           // 0..31
    const int b    = bh / Hh;
    const int h    = bh % Hh;
    const int m0   = w * 16;               // warp's q-row base within tile

    const float scale = 0.08838834764831845f;   // 1/sqrt(128)
    const float NEG   = -3.402823466e38f;

    // ---- stage mask row for this batch (2048 floats) ----
    #pragma unroll
    for (int i = 0; i < 2; i++) {
        int c = t + 256 * i;
        *(float4*)&maskrow[c * 4] = *(const float4*)&mask[b * Sq + c * 4];
    }

    // ---- stage Q tile (128 rows x 64 words) into K buffers, then to regs ----
    #pragma unroll
    for (int i = 0; i < 8; i++) {
        int c = t + 256 * i;               // 2048 chunks
        int r = c >> 4, cw = (c & 15) * 4;
        size_t goff = (size_t)(b * Sq + qt * 128 + r) * (HID/2) + h * (Dd/2) + cw;
        *(uint4*)&Kh0[r * 68 + cw] = *(const uint4*)&g_q_hi[goff];
        *(uint4*)&Kl0[r * 68 + cw] = *(const uint4*)&g_q_lo[goff];
    }
    __syncthreads();

    unsigned qh[8][4], ql[8][4];
    #pragma unroll
    for (int kf = 0; kf < 8; kf++) {
        qh[kf][0] = Kh0[(m0 + g    ) * 68 + kf * 8 + tig];
        qh[kf][1] = Kh0[(m0 + g + 8) * 68 + kf * 8 + tig];
        qh[kf][2] = Kh0[(m0 + g    ) * 68 + kf * 8 + 4 + tig];
        qh[kf][3] = Kh0[(m0 + g + 8) * 68 + kf * 8 + 4 + tig];
        ql[kf][0] = Kl0[(m0 + g    ) * 68 + kf * 8 + tig];
        ql[kf][1] = Kl0[(m0 + g + 8) * 68 + kf * 8 + tig];
        ql[kf][2] = Kl0[(m0 + g    ) * 68 + kf * 8 + 4 + tig];
        ql[kf][3] = Kl0[(m0 + g + 8) * 68 + kf * 8 + 4 + tig];
    }
    __syncthreads();

    // ---- pipeline state ----
    float o[16][4];
    #pragma unroll
    for (int nd = 0; nd < 16; nd++)
        #pragma unroll
        for (int q = 0; q < 4; q++) o[nd][q] = 0.f;
    float mrow0 = -INFINITY, mrow1 = -INFINITY;
    float lsum0 = 0.f, lsum1 = 0.f;

    const unsigned* Vhw = (const unsigned*)g_vT_hi;
    const unsigned* Vlw = (const unsigned*)g_vT_lo;

    // issue tile kt into buffer bi
    auto issue = [&](int kt, int bi) {
        unsigned dKh = sbase + (bi * KBUF) * 4;
        unsigned dKl = sbase + (2*KBUF + bi * KBUF) * 4;
        unsigned dVh = sbase + (4*KBUF + bi * VBUF) * 4;
        unsigned dVl = sbase + (4*KBUF + 2*VBUF + bi * VBUF) * 4;
        #pragma unroll
        for (int i = 0; i < 4; i++) {
            int c = t + 256 * i;               // 1024 K chunks
            int r = c >> 4, cw = (c & 15) * 4;
            size_t goff = (size_t)(b * Sq + kt * 64 + r) * (Dd/2) + cw;
            cp16(dKh + (r * 68 + cw) * 4, &g_k_hi[goff]);
            cp16(dKl + (r * 68 + cw) * 4, &g_k_lo[goff]);
        }
        #pragma unroll
        for (int i = 0; i < 4; i++) {
            int c = t + 256 * i;               // 1024 V chunks
            int r = c >> 3, cw = (c & 7) * 4;
            size_t goff = (size_t)r * (MM/2) + (size_t)(b * Sq + kt * 64) / 2 + cw;
            cp16(dVh + (r * 36 + cw) * 4, &Vhw[goff]);
            cp16(dVl + (r * 36 + cw) * 4, &Vlw[goff]);
        }
    };

    issue(0, 0);
    cp_commit();

    for (int kt = 0; kt < NT_TILES; kt++) {
        const int bi = kt & 1;
        if (kt + 1 < NT_TILES) {
            issue(kt + 1, bi ^ 1);
            cp_commit();
            cp_wait<1>();
        } else {
            cp_wait<0>();
        }
        __syncthreads();

        unsigned* Kh = Kh0 + bi * KBUF;
        unsigned* Kl = Kl0 + bi * KBUF;
        unsigned* Vh = Vh0 + bi * VBUF;
        unsigned* Vl = Vl0 + bi * VBUF;

        // ----- QK^T : warp computes its 16 rows x 64 keys
        float s[8][4];
        #pragma unroll
        for (int nt = 0; nt < 8; nt++)
            #pragma unroll
            for (int q = 0; q < 4; q++) s[nt][q] = 0.f;

        #pragma unroll
        for (int kf = 0; kf < 8; kf++) {
            #pragma unroll
            for (int nt = 0; nt < 8; nt++) {
                int nc = nt * 8 + g;
                unsigned bh0 = Kh[nc * 68 + kf * 8 + tig];
                unsigned bh1 = Kh[nc * 68 + kf * 8 + 4 + tig];
                unsigned bl0 = Kl[nc * 68 + kf * 8 + tig];
                unsigned bl1 = Kl[nc * 68 + kf * 8 + 4 + tig];
                mma_bf16(s[nt], qh[kf][0], qh[kf][1], qh[kf][2], qh[kf][3], bl0, bl1);
                mma_bf16(s[nt], ql[kf][0], ql[kf][1], ql[kf][2], ql[kf][3], bh0, bh1);
                mma_bf16(s[nt], qh[kf][0], qh[kf][1], qh[kf][2], qh[kf][3], bh0, bh1);
            }
        }

        // ----- scale + mask + register softmax (quad-level reductions)
        float m0new = -INFINITY, m1new = -INFINITY;
        #pragma unroll
        for (int nt = 0; nt < 8; nt++) {
            int c0 = kt * 64 + nt * 8 + tig * 2;
            float mt0 = (1.0f - maskrow[c0])     * NEG;
            float mt1 = (1.0f - maskrow[c0 + 1]) * NEG;
            s[nt][0] = s[nt][0] * scale + mt0;
            s[nt][1] = s[nt][1] * scale + mt1;
            s[nt][2] = s[nt][2] * scale + mt0;
            s[nt][3] = s[nt][3] * scale + mt1;
            m0new = fmaxf(m0new, fmaxf(s[nt][0], s[nt][1]));
            m1new = fmaxf(m1new, fmaxf(s[nt][2], s[nt][3]));
        }
        m0new = fmaxf(m0new, __shfl_xor_sync(0xffffffffu, m0new, 1));
        m0new = fmaxf(m0new, __shfl_xor_sync(0xffffffffu, m0new, 2));
        m1new = fmaxf(m1new, __shfl_xor_sync(0xffffffffu, m1new, 1));
        m1new = fmaxf(m1new, __shfl_xor_sync(0xffffffffu, m1new, 2));

        float newm0 = fmaxf(mrow0, m0new);
        float newm1 = fmaxf(mrow1, m1new);
        float corr0 = __expf(mrow0 - newm0);
        float corr1 = __expf(mrow1 - newm1);
        mrow0 = newm0; mrow1 = newm1;

        float ps0 = 0.f, ps1 = 0.f;
        #pragma unroll
        for (int nt = 0; nt < 8; nt++) {
            s[nt][0] = __expf(s[nt][0] - newm0);
            s[nt][1] = __expf(s[nt][1] - newm0);
            s[nt][2] = __expf(s[nt][2] - newm1);
            s[nt][3] = __expf(s[nt][3] - newm1);
            ps0 += s[nt][0] + s[nt][1];
            ps1 += s[nt][2] + s[nt][3];
        }
        ps0 += __shfl_xor_sync(0xffffffffu, ps0, 1);
        ps0 += __shfl_xor_sync(0xffffffffu, ps0, 2);
        ps1 += __shfl_xor_sync(0xffffffffu, ps1, 1);
        ps1 += __shfl_xor_sync(0xffffffffu, ps1, 2);
        lsum0 = lsum0 * corr0 + ps0;
        lsum1 = lsum1 * corr1 + ps1;

        #pragma unroll
        for (int nd = 0; nd < 16; nd++) {
            o[nd][0] *= corr0; o[nd][1] *= corr0;
            o[nd][2] *= corr1; o[nd][3] *= corr1;
        }

        // ----- PV : P frags built in registers (FA2 layout identity)
        #pragma unroll
        for (int kf = 0; kf < 4; kf++) {
            unsigned a0h, a0l, a1h, a1l, a2h, a2l, a3h, a3l;
            split2(s[2*kf  ][0], s[2*kf  ][1], a0h, a0l);
            split2(s[2*kf  ][2], s[2*kf  ][3], a1h, a1l);
            split2(s[2*kf+1][0], s[2*kf+1][1], a2h, a2l);
            split2(s[2*kf+1][2], s[2*kf+1][3], a3h, a3l);
            #pragma unroll
            for (int nd = 0; nd < 16; nd++) {
                int nc = nd * 8 + g;
                unsigned bh0 = Vh[nc * 36 + kf * 8 + tig];
                unsigned bh1 = Vh[nc * 36 + kf * 8 + 4 + tig];
                unsigned bl0 = Vl[nc * 36 + kf * 8 + tig];
                unsigned bl1 = Vl[nc * 36 + kf * 8 + 4 + tig];
                mma_bf16(o[nd], a0h, a1h, a2h, a3h, bl0, bl1);
                mma_bf16(o[nd], a0l, a1l, a2l, a3l, bh0, bh1);
                mma_bf16(o[nd], a0h, a1h, a2h, a3h, bh0, bh1);
            }
        }
        __syncthreads();
    }

    // ---- epilogue: normalize, split, write packed hi/lo [s][hd] ----
    float inv0 = 1.0f / lsum0;
    float inv1 = 1.0f / lsum1;
    size_t row0 = (size_t)(b * Sq + qt * 128 + m0 + g);
    #pragma unroll
    for (int nd = 0; nd < 16; nd++) {
        int cw = h * (Dd/2) + nd * 4 + tig;
        unsigned hh, llw;
        split2(o[nd][0] * inv0, o[nd][1] * inv0, hh, llw);
        g_a_hi[row0 * (HID/2) + cw] = hh;
        g_a_lo[row0 * (HID/2) + cw] = llw;
        split2(o[nd][2] * inv1, o[nd][3] * inv1, hh, llw);
        g_a_hi[(row0 + 8) * (HID/2) + cw] = hh;
        g_a_lo[(row0 + 8) * (HID/2) + cw] = llw;
    }
}

// ---------------------------------------------------------------------------
// KV cache broadcast: key/value outputs replicate k/v over 16 heads.
// ---------------------------------------------------------------------------
__global__ __launch_bounds__(256)
void kv_broadcast(float* __restrict__ out)
{
    int i = blockIdx.x * 256 + threadIdx.x;   // float4 index, 131072 total
    int o = i * 4;
    int b = o / (Sq * Dd);
    int rem = o - b * Sq * Dd;
    int s = rem / Dd;
    int d = rem - s * Dd;
    float4 kv = *(const float4*)&g_k[o];
    float4 vv = *(const float4*)&g_v[o];
    const size_t keybase = (size_t)MM * HID;                       // 8388608
    const size_t valbase = keybase + (size_t)Bz * Hh * Sq * Dd;    // 16777216
    #pragma unroll
    for (int h = 0; h < Hh; h++) {
        size_t idx = (((size_t)b * Hh + h) * Sq + s) * Dd + d;
        *(float4*)&out[keybase + idx] = kv;
        *(float4*)&out[valbase + idx] = vv;
    }
}

// ---------------------------------------------------------------------------
extern "C" void kernel_launch(void* const* d_in, const int* in_sizes, int n_in,
                              void* d_out, int out_size)
{
    const float* hs   = (const float*)d_in[0];
    const float* mask = (const float*)d_in[1];
    const float* Wq   = (const float*)d_in[2];
    const float* Wk   = (const float*)d_in[3];
    const float* Wv   = (const float*)d_in[4];
    const float* Wo   = (const float*)d_in[5];
    float* out = (float*)d_out;

    void *pqh, *pql;
    cudaGetSymbolAddress(&pqh, g_q_hi);
    cudaGetSymbolAddress(&pql, g_q_lo);

    static int smem_set = 0;
    if (!smem_set) {
        cudaFuncSetAttribute(attn_kernel, cudaFuncAttributeMaxDynamicSharedMemorySize,
                             ATTN_SMEM_WORDS * 4);
        smem_set = 1;
    }

    dim3 blk(256);
    // Q projection -> packed hi/lo
    gemm_q<<<dim3(HID / BN, MM / BM), blk>>>(hs, Wq, (unsigned*)pqh, (unsigned*)pql,
                                             MM, HID, HID);
    // K + V projections (fp32 + split forms)
    gemm_kv<<<dim3(1, MM / BM, 2), blk>>>(hs, Wk, Wv, MM, Dd, HID);
    // KV cache broadcast outputs
    kv_broadcast<<<(MM * Dd / 4 + 255) / 256, blk>>>(out);
    // fused attention (FA2-style)
    attn_kernel<<<dim3(Sq / 128, Bz * Hh), blk, ATTN_SMEM_WORDS * 4>>>(mask);
    // output projection -> out[0 : 8388608]
    gemm_o<<<dim3(HID / BN, MM / BM), blk>>>(Wo, out, MM, HID, HID);
}

// round 7
// speedup vs baseline: 3.7371x; 1.1501x over previous
#include <cuda_runtime.h>
#include <cuda_bf16.h>
#include <math.h>

#define Bz   2
#define Sq   2048
#define Hh   16
#define Dd   128
#define HID  2048
#define MM   (Bz*Sq)        // 4096

// ---------------- scratch (static device globals; no allocs) ----------------
// All "hi/lo" arrays hold packed bf16x2 words in PERMUTED k-group order:
// within each group of 8 words (16 k-values), storage order is
// [w0,w4,w1,w5,w2,w6,w3,w7] so mma frag pairs (tig, tig+4) are adjacent.
__device__ unsigned g_hs_hi[MM*(HID/2)],  g_hs_lo[MM*(HID/2)];    // split hidden_states
__device__ unsigned g_wq_hi[HID*(HID/2)], g_wq_lo[HID*(HID/2)];   // split Wq
__device__ unsigned g_wk_hi[Dd*(HID/2)],  g_wk_lo[Dd*(HID/2)];    // split Wk
__device__ unsigned g_wv_hi[Dd*(HID/2)],  g_wv_lo[Dd*(HID/2)];    // split Wv
__device__ unsigned g_wo_hi[HID*(HID/2)], g_wo_lo[HID*(HID/2)];   // split Wo
__device__ unsigned g_q_hi[MM*(HID/2)],   g_q_lo[MM*(HID/2)];     // Q proj
__device__ float    g_k[MM*Dd];                                    // K fp32 (cache)
__device__ unsigned g_k_hi[MM*(Dd/2)],    g_k_lo[MM*(Dd/2)];      // K split
__device__ float    g_v[MM*Dd];                                    // V fp32 (cache)
__device__ __nv_bfloat16 g_vT_hi[Dd*MM],  g_vT_lo[Dd*MM];         // V^T split [d][s]
__device__ unsigned g_a_hi[MM*(HID/2)],   g_a_lo[MM*(HID/2)];     // attn out

// ---------------------------------------------------------------------------
// helpers
// ---------------------------------------------------------------------------
__device__ __forceinline__ void split2(float x0, float x1, unsigned& hi, unsigned& lo)
{
    __nv_bfloat16 h0 = __float2bfloat16(x0);
    __nv_bfloat16 h1 = __float2bfloat16(x1);
    __nv_bfloat16 l0 = __float2bfloat16(x0 - __bfloat162float(h0));
    __nv_bfloat16 l1 = __float2bfloat16(x1 - __bfloat162float(h1));
    hi = ((unsigned)__bfloat16_as_ushort(h1) << 16) | (unsigned)__bfloat16_as_ushort(h0);
    lo = ((unsigned)__bfloat16_as_ushort(l1) << 16) | (unsigned)__bfloat16_as_ushort(l0);
}

__device__ __forceinline__ void mma_bf16(float c[4],
    unsigned a0, unsigned a1, unsigned a2, unsigned a3,
    unsigned b0, unsigned b1)
{
    asm volatile(
        "mma.sync.aligned.m16n8k16.row.col.f32.bf16.bf16.f32 "
        "{%0,%1,%2,%3}, {%4,%5,%6,%7}, {%8,%9}, {%0,%1,%2,%3};"
        : "+f"(c[0]), "+f"(c[1]), "+f"(c[2]), "+f"(c[3])
        : "r"(a0), "r"(a1), "r"(a2), "r"(a3), "r"(b0), "r"(b1));
}

__device__ __forceinline__ void cp16(unsigned dst, const void* src)
{
    asm volatile("cp.async.cg.shared.global [%0], [%1], 16;" :: "r"(dst), "l"(src));
}
__device__ __forceinline__ void cp_commit()
{
    asm volatile("cp.async.commit_group;");
}
template<int N>
__device__ __forceinline__ void cp_wait()
{
    asm volatile("cp.async.wait_group %0;" :: "n"(N));
}

// permute word index within its 8-word group: w&7 -> slot
__device__ __forceinline__ int permw(int w)
{
    int ww = w & 7;
    int slot = (ww < 4) ? (2 * ww) : (2 * ww - 7);
    return (w & ~7) | slot;
}

// ---------------------------------------------------------------------------
// presplit: fp32 [R,K] -> hi/lo packed words in permuted group order
// one thread per 8-word group (16 floats)
// ---------------------------------------------------------------------------
__global__ __launch_bounds__(256)
void presplit(const float* __restrict__ X, unsigned* __restrict__ Hi,
              unsigned* __restrict__ Lo, int ngroups)
{
    int gi = blockIdx.x * 256 + threadIdx.x;
    if (gi >= ngroups) return;
    const float4* src = (const float4*)X + (size_t)gi * 4;
    unsigned wh[8], wl[8];
    #pragma unroll
    for (int i = 0; i < 4; i++) {
        float4 v = src[i];
        split2(v.x, v.y, wh[2*i],   wl[2*i]);
        split2(v.z, v.w, wh[2*i+1], wl[2*i+1]);
    }
    uint4 h0 = {wh[0], wh[4], wh[1], wh[5]};
    uint4 h1 = {wh[2], wh[6], wh[3], wh[7]};
    uint4 l0 = {wl[0], wl[4], wl[1], wl[5]};
    uint4 l1 = {wl[2], wl[6], wl[3], wl[7]};
    ((uint4*)Hi)[(size_t)gi*2]   = h0;  ((uint4*)Hi)[(size_t)gi*2+1] = h1;
    ((uint4*)Lo)[(size_t)gi*2]   = l0;  ((uint4*)Lo)[(size_t)gi*2+1] = l1;
}

// ---------------------------------------------------------------------------
// 3xBF16 GEMM core v2: all operands pre-split+permuted in gmem.
// 128x128 block, BK=32 (16 words), 256 threads (8 warps 4x2),
// cp.async 2-stage double buffer, LDS.64 fragment loads.
// ---------------------------------------------------------------------------
#define BM 128
#define BN 128
#define GWS 24            // words per smem row (16 data + 8 pad; 24%32==24 -> CF for LDS.64)
#define GST (BM*GWS)      // 3072 words per buffer stage
#define GEMM_SMEM_BYTES (8*GST*4)   // 98304

__device__ __forceinline__ void gemm_core2(
    const unsigned* __restrict__ Ahi, const unsigned* __restrict__ Alo,
    const unsigned* __restrict__ Bhi, const unsigned* __restrict__ Blo,
    int KW, int bm, int bn, unsigned* dsm, float acc[2][8][4])
{
    unsigned* sAh = dsm;
    unsigned* sAl = dsm + 2*GST;
    unsigned* sBh = dsm + 4*GST;
    unsigned* sBl = dsm + 6*GST;
    const unsigned sbase = (unsigned)__cvta_generic_to_shared(dsm);

    const int t    = threadIdx.x;
    const int lane = t & 31, w = t >> 5;
    const int g    = lane >> 2, tig = lane & 3;
    const int wm   = w >> 1, wn = w & 1;

    #pragma unroll
    for (int i = 0; i < 2; i++)
        #pragma unroll
        for (int j = 0; j < 8; j++)
            #pragma unroll
            for (int q = 0; q < 4; q++) acc[i][j][q] = 0.f;

    const int cr = t >> 2, cc4 = (t & 3) * 4;   // chunk row 0..63, word col
    // each thread: rows cr and cr+64 (2 chunks per operand-half)
    auto issue = [&](int it, int bi) {
        const int kw0 = it * 16;
        unsigned dAh = sbase + (0*GST*2 + bi*GST) * 4;
        unsigned dAl = sbase + (1*GST*2 + bi*GST) * 4;
        unsigned dBh = sbase + (2*GST*2 + bi*GST) * 4;
        unsigned dBl = sbase + (3*GST*2 + bi*GST) * 4;
        #pragma unroll
        for (int i = 0; i < 2; i++) {
            int r = cr + 64 * i;
            size_t ao = (size_t)(bm + r) * KW + kw0 + cc4;
            size_t bo = (size_t)(bn + r) * KW + kw0 + cc4;
            unsigned so = (r * GWS + cc4) * 4;
            cp16(dAh + so, &Ahi[ao]);
            cp16(dAl + so, &Alo[ao]);
            cp16(dBh + so, &Bhi[bo]);
            cp16(dBl + so, &Blo[bo]);
        }
    };

    const int niter = KW / 16;
    issue(0, 0);
    cp_commit();

    for (int it = 0; it < niter; it++) {
        if (it + 1 < niter) { issue(it + 1, (it + 1) & 1); cp_commit(); cp_wait<1>(); }
        else                { cp_wait<0>(); }
        __syncthreads();

        const int bi = it & 1;
        const unsigned* pAh = sAh + bi * GST;
        const unsigned* pAl = sAl + bi * GST;
        const unsigned* pBh = sBh + bi * GST;
        const unsigned* pBl = sBl + bi * GST;

        #pragma unroll
        for (int ks = 0; ks < 2; ks++) {
            const int kb = ks * 8 + 2 * tig;
            uint2 ah0[2], ah1[2], al0[2], al1[2];
            #pragma unroll
            for (int mt = 0; mt < 2; mt++) {
                int m0r = wm * 32 + mt * 16;
                ah0[mt] = *(const uint2*)&pAh[(m0r + g    ) * GWS + kb];
                ah1[mt] = *(const uint2*)&pAh[(m0r + g + 8) * GWS + kb];
                al0[mt] = *(const uint2*)&pAl[(m0r + g    ) * GWS + kb];
                al1[mt] = *(const uint2*)&pAl[(m0r + g + 8) * GWS + kb];
            }
            #pragma unroll
            for (int nt = 0; nt < 8; nt++) {
                int nc = wn * 64 + nt * 8 + g;
                uint2 bhp = *(const uint2*)&pBh[nc * GWS + kb];
                uint2 blp = *(const uint2*)&pBl[nc * GWS + kb];
                #pragma unroll
                for (int mt = 0; mt < 2; mt++) {
                    mma_bf16(acc[mt][nt], ah0[mt].x, ah1[mt].x, ah0[mt].y, ah1[mt].y, blp.x, blp.y);
                    mma_bf16(acc[mt][nt], al0[mt].x, al1[mt].x, al0[mt].y, al1[mt].y, bhp.x, bhp.y);
                    mma_bf16(acc[mt][nt], ah0[mt].x, ah1[mt].x, ah0[mt].y, ah1[mt].y, bhp.x, bhp.y);
                }
            }
        }
        __syncthreads();
    }
}

// ---- Q projection: writes split+permuted g_q ------------------------------
__global__ __launch_bounds__(256, 2)
void gemm_q2(int M, int N, int K)
{
    extern __shared__ unsigned dsm[];
    float acc[2][8][4];
    const int bm = blockIdx.y * BM, bn = blockIdx.x * BN;
    gemm_core2(g_hs_hi, g_hs_lo, g_wq_hi, g_wq_lo, K >> 1, bm, bn, dsm, acc);

    const int t = threadIdx.x, lane = t & 31, w = t >> 5;
    const int g = lane >> 2, tig = lane & 3;
    const int wm = w >> 1, wn = w & 1;
    const int NW = N >> 1;
    #pragma unroll
    for (int mt = 0; mt < 2; mt++) {
        int r0 = bm + wm * 32 + mt * 16 + g;
        #pragma unroll
        for (int nt = 0; nt < 8; nt++) {
            int wp = permw((bn >> 1) + wn * 32 + nt * 4 + tig);
            unsigned h0, l0;
            split2(acc[mt][nt][0], acc[mt][nt][1], h0, l0);
            g_q_hi[(size_t)r0 * NW + wp] = h0;
            g_q_lo[(size_t)r0 * NW + wp] = l0;
            split2(acc[mt][nt][2], acc[mt][nt][3], h0, l0);
            g_q_hi[(size_t)(r0 + 8) * NW + wp] = h0;
            g_q_lo[(size_t)(r0 + 8) * NW + wp] = l0;
        }
    }
}

// ---- K + V projections (z=0 -> K, z=1 -> V) -------------------------------
__global__ __launch_bounds__(256, 2)
void gemm_kv2(int M, int N, int K)
{
    extern __shared__ unsigned dsm[];
    float acc[2][8][4];
    const int bm = blockIdx.y * BM, bn = 0;
    const unsigned* Bh = blockIdx.z ? g_wv_hi : g_wk_hi;
    const unsigned* Bl = blockIdx.z ? g_wv_lo : g_wk_lo;
    gemm_core2(g_hs_hi, g_hs_lo, Bh, Bl, K >> 1, bm, bn, dsm, acc);

    const int t = threadIdx.x, lane = t & 31, w = t >> 5;
    const int g = lane >> 2, tig = lane & 3;
    const int wm = w >> 1, wn = w & 1;
    const int NW = N >> 1;
    #pragma unroll
    for (int mt = 0; mt < 2; mt++) {
        int r0 = bm + wm * 32 + mt * 16 + g;
        #pragma unroll
        for (int nt = 0; nt < 8; nt++) {
            int c0 = wn * 64 + nt * 8 + tig * 2;
            float a0 = acc[mt][nt][0], a1 = acc[mt][nt][1];
            float a2 = acc[mt][nt][2], a3 = acc[mt][nt][3];
            if (blockIdx.z == 0) {
                *(float2*)&g_k[(size_t)r0 * N + c0]       = make_float2(a0, a1);
                *(float2*)&g_k[(size_t)(r0 + 8) * N + c0] = make_float2(a2, a3);
                int wp = permw(c0 >> 1);
                unsigned h0, l0;
                split2(a0, a1, h0, l0);
                g_k_hi[(size_t)r0 * NW + wp] = h0;
                g_k_lo[(size_t)r0 * NW + wp] = l0;
                split2(a2, a3, h0, l0);
                g_k_hi[(size_t)(r0 + 8) * NW + wp] = h0;
                g_k_lo[(size_t)(r0 + 8) * NW + wp] = l0;
            } else {
                *(float2*)&g_v[(size_t)r0 * N + c0]       = make_float2(a0, a1);
                *(float2*)&g_v[(size_t)(r0 + 8) * N + c0] = make_float2(a2, a3);
                #pragma unroll
                for (int q = 0; q < 4; q++) {
                    float val = acc[mt][nt][q];
                    int cc = c0 + (q & 1);
                    int rr = r0 + (q >> 1) * 8;
                    // permuted element position along s
                    int sp = permw(rr >> 1) * 2 + (rr & 1);
                    __nv_bfloat16 hh = __float2bfloat16(val);
                    __nv_bfloat16 ll = __float2bfloat16(val - __bfloat162float(hh));
                    g_vT_hi[(size_t)cc * MM + sp] = hh;
                    g_vT_lo[(size_t)cc * MM + sp] = ll;
                }
            }
        }
    }
}

// ---- O projection: fp32 output --------------------------------------------
__global__ __launch_bounds__(256, 2)
void gemm_o2(float* __restrict__ C, int M, int N, int K)
{
    extern __shared__ unsigned dsm[];
    float acc[2][8][4];
    const int bm = blockIdx.y * BM, bn = blockIdx.x * BN;
    gemm_core2(g_a_hi, g_a_lo, g_wo_hi, g_wo_lo, K >> 1, bm, bn, dsm, acc);

    const int t = threadIdx.x, lane = t & 31, w = t >> 5;
    const int g = lane >> 2, tig = lane & 3;
    const int wm = w >> 1, wn = w & 1;
    #pragma unroll
    for (int mt = 0; mt < 2; mt++) {
        int r0 = bm + wm * 32 + mt * 16 + g;
        #pragma unroll
        for (int nt = 0; nt < 8; nt++) {
            int c0 = bn + wn * 64 + nt * 8 + tig * 2;
            *(float2*)&C[(size_t)r0 * N + c0]       = make_float2(acc[mt][nt][0], acc[mt][nt][1]);
            *(float2*)&C[(size_t)(r0 + 8) * N + c0] = make_float2(acc[mt][nt][2], acc[mt][nt][3]);
        }
    }
}

// ---------------------------------------------------------------------------
// FlashAttention-2: 128 q rows/block, warp owns 16 rows, register softmax,
// cp.async double-buffered K/V, LDS.64 frag loads on permuted layout.
// K/Q smem rows: 64 data + 8 pad = 72 words (72%32==8 -> CF for LDS.64)
// V smem rows:   32 data + 8 pad = 40 words (40%32==8 -> CF)
// ---------------------------------------------------------------------------
#define KROW 72
#define VROW 40
#define KBUF (64*KROW)     // 4608
#define VBUF (128*VROW)    // 5120
#define ATTN_SMEM_WORDS (4*KBUF + 4*VBUF + Sq)   // 40960
#define NT_TILES (Sq/64)

__global__ __launch_bounds__(256, 1)
void attn_kernel(const float* __restrict__ mask)
{
    extern __shared__ unsigned smw[];
    unsigned* Kh0 = smw;
    unsigned* Kl0 = smw + 2*KBUF;
    unsigned* Vh0 = smw + 4*KBUF;
    unsigned* Vl0 = smw + 4*KBUF + 2*VBUF;
    float*  maskrow = (float*)(smw + 4*KBUF + 4*VBUF);

    const unsigned sbase = (unsigned)__cvta_generic_to_shared(smw);

    const int t    = threadIdx.x;
    const int lane = t & 31, w = t >> 5;
    const int g    = lane >> 2, tig = lane & 3;
    const int qt   = blockIdx.x;           // 0..15
    const int bh   = blockIdx.y;           // 0..31
    const int b    = bh / Hh;
    const int h    = bh % Hh;
    const int m0   = w * 16;

    const float scale = 0.08838834764831845f;   // 1/sqrt(128)
    const float NEG   = -3.402823466e38f;

    // ---- stage mask row (2048 floats) ----
    #pragma unroll
    for (int i = 0; i < 2; i++) {
        int c = t + 256 * i;
        *(float4*)&maskrow[c * 4] = *(const float4*)&mask[b * Sq + c * 4];
    }

    // ---- stage Q tile (128 rows x 64 words) into K buffers, then to regs ----
    #pragma unroll
    for (int i = 0; i < 8; i++) {
        int c = t + 256 * i;               // 2048 chunks
        int r = c >> 4, cw = (c & 15) * 4;
        size_t goff = (size_t)(b * Sq + qt * 128 + r) * (HID/2) + h * (Dd/2) + cw;
        *(uint4*)&Kh0[r * KROW + cw] = *(const uint4*)&g_q_hi[goff];
        *(uint4*)&Kl0[r * KROW + cw] = *(const uint4*)&g_q_lo[goff];
    }
    __syncthreads();

    unsigned qh[8][4], ql[8][4];
    #pragma unroll
    for (int kf = 0; kf < 8; kf++) {
        int kb = kf * 8 + 2 * tig;
        uint2 p0 = *(const uint2*)&Kh0[(m0 + g    ) * KROW + kb];
        uint2 p1 = *(const uint2*)&Kh0[(m0 + g + 8) * KROW + kb];
        qh[kf][0] = p0.x; qh[kf][1] = p1.x; qh[kf][2] = p0.y; qh[kf][3] = p1.y;
        p0 = *(const uint2*)&Kl0[(m0 + g    ) * KROW + kb];
        p1 = *(const uint2*)&Kl0[(m0 + g + 8) * KROW + kb];
        ql[kf][0] = p0.x; ql[kf][1] = p1.x; ql[kf][2] = p0.y; ql[kf][3] = p1.y;
    }
    __syncthreads();

    float o[16][4];
    #pragma unroll
    for (int nd = 0; nd < 16; nd++)
        #pragma unroll
        for (int q = 0; q < 4; q++) o[nd][q] = 0.f;
    float mrow0 = -INFINITY, mrow1 = -INFINITY;
    float lsum0 = 0.f, lsum1 = 0.f;

    const unsigned* Vhw = (const unsigned*)g_vT_hi;
    const unsigned* Vlw = (const unsigned*)g_vT_lo;

    auto issue = [&](int kt, int bi) {
        unsigned dKh = sbase + (bi * KBUF) * 4;
        unsigned dKl = sbase + (2*KBUF + bi * KBUF) * 4;
        unsigned dVh = sbase + (4*KBUF + bi * VBUF) * 4;
        unsigned dVl = sbase + (4*KBUF + 2*VBUF + bi * VBUF) * 4;
        #pragma unroll
        for (int i = 0; i < 4; i++) {
            int c = t + 256 * i;               // 1024 K chunks
            int r = c >> 4, cw = (c & 15) * 4;
            size_t goff = (size_t)(b * Sq + kt * 64 + r) * (Dd/2) + cw;
            cp16(dKh + (r * KROW + cw) * 4, &g_k_hi[goff]);
            cp16(dKl + (r * KROW + cw) * 4, &g_k_lo[goff]);
        }
        #pragma unroll
        for (int i = 0; i < 4; i++) {
            int c = t + 256 * i;               // 1024 V chunks
            int r = c >> 3, cw = (c & 7) * 4;
            size_t goff = (size_t)r * (MM/2) + (size_t)(b * Sq + kt * 64) / 2 + cw;
            cp16(dVh + (r * VROW + cw) * 4, &Vhw[goff]);
            cp16(dVl + (r * VROW + cw) * 4, &Vlw[goff]);
        }
    };

    issue(0, 0);
    cp_commit();

    for (int kt = 0; kt < NT_TILES; kt++) {
        const int bi = kt & 1;
        if (kt + 1 < NT_TILES) { issue(kt + 1, bi ^ 1); cp_commit(); cp_wait<1>(); }
        else                   { cp_wait<0>(); }
        __syncthreads();

        unsigned* Kh = Kh0 + bi * KBUF;
        unsigned* Kl = Kl0 + bi * KBUF;
        unsigned* Vh = Vh0 + bi * VBUF;
        unsigned* Vl = Vl0 + bi * VBUF;

        // ----- QK^T
        float s[8][4];
        #pragma unroll
        for (int nt = 0; nt < 8; nt++)
            #pragma unroll
            for (int q = 0; q < 4; q++) s[nt][q] = 0.f;

        #pragma unroll
        for (int kf = 0; kf < 8; kf++) {
            const int kb = kf * 8 + 2 * tig;
            #pragma unroll
            for (int nt = 0; nt < 8; nt++) {
                int nc = nt * 8 + g;
                uint2 bhp = *(const uint2*)&Kh[nc * KROW + kb];
                uint2 blp = *(const uint2*)&Kl[nc * KROW + kb];
                mma_bf16(s[nt], qh[kf][0], qh[kf][1], qh[kf][2], qh[kf][3], blp.x, blp.y);
                mma_bf16(s[nt], ql[kf][0], ql[kf][1], ql[kf][2], ql[kf][3], bhp.x, bhp.y);
                mma_bf16(s[nt], qh[kf][0], qh[kf][1], qh[kf][2], qh[kf][3], bhp.x, bhp.y);
            }
        }

        // ----- scale + mask + register softmax
        float m0new = -INFINITY, m1new = -INFINITY;
        #pragma unroll
        for (int nt = 0; nt < 8; nt++) {
            int c0 = kt * 64 + nt * 8 + tig * 2;
            float mt0 = (1.0f - maskrow[c0])     * NEG;
            float mt1 = (1.0f - maskrow[c0 + 1]) * NEG;
            s[nt][0] = s[nt][0] * scale + mt0;
            s[nt][1] = s[nt][1] * scale + mt1;
            s[nt][2] = s[nt][2] * scale + mt0;
            s[nt][3] = s[nt][3] * scale + mt1;
            m0new = fmaxf(m0new, fmaxf(s[nt][0], s[nt][1]));
            m1new = fmaxf(m1new, fmaxf(s[nt][2], s[nt][3]));
        }
        m0new = fmaxf(m0new, __shfl_xor_sync(0xffffffffu, m0new, 1));
        m0new = fmaxf(m0new, __shfl_xor_sync(0xffffffffu, m0new, 2));
        m1new = fmaxf(m1new, __shfl_xor_sync(0xffffffffu, m1new, 1));
        m1new = fmaxf(m1new, __shfl_xor_sync(0xffffffffu, m1new, 2));

        float newm0 = fmaxf(mrow0, m0new);
        float newm1 = fmaxf(mrow1, m1new);
        float corr0 = __expf(mrow0 - newm0);
        float corr1 = __expf(mrow1 - newm1);
        mrow0 = newm0; mrow1 = newm1;

        float ps0 = 0.f, ps1 = 0.f;
        #pragma unroll
        for (int nt = 0; nt < 8; nt++) {
            s[nt][0] = __expf(s[nt][0] - newm0);
            s[nt][1] = __expf(s[nt][1] - newm0);
            s[nt][2] = __expf(s[nt][2] - newm1);
            s[nt][3] = __expf(s[nt][3] - newm1);
            ps0 += s[nt][0] + s[nt][1];
            ps1 += s[nt][2] + s[nt][3];
        }
        ps0 += __shfl_xor_sync(0xffffffffu, ps0, 1);
        ps0 += __shfl_xor_sync(0xffffffffu, ps0, 2);
        ps1 += __shfl_xor_sync(0xffffffffu, ps1, 1);
        ps1 += __shfl_xor_sync(0xffffffffu, ps1, 2);
        lsum0 = lsum0 * corr0 + ps0;
        lsum1 = lsum1 * corr1 + ps1;

        #pragma unroll
        for (int nd = 0; nd < 16; nd++) {
            o[nd][0] *= corr0; o[nd][1] *= corr0;
            o[nd][2] *= corr1; o[nd][3] *= corr1;
        }

        // ----- PV
        #pragma unroll
        for (int kf = 0; kf < 4; kf++) {
            unsigned a0h, a0l, a1h, a1l, a2h, a2l, a3h, a3l;
            split2(s[2*kf  ][0], s[2*kf  ][1], a0h, a0l);
            split2(s[2*kf  ][2], s[2*kf  ][3], a1h, a1l);
            split2(s[2*kf+1][0], s[2*kf+1][1], a2h, a2l);
            split2(s[2*kf+1][2], s[2*kf+1][3], a3h, a3l);
            const int kb = kf * 8 + 2 * tig;
            #pragma unroll
            for (int nd = 0; nd < 16; nd++) {
                int nc = nd * 8 + g;
                uint2 bhp = *(const uint2*)&Vh[nc * VROW + kb];
                uint2 blp = *(const uint2*)&Vl[nc * VROW + kb];
                mma_bf16(o[nd], a0h, a1h, a2h, a3h, blp.x, blp.y);
                mma_bf16(o[nd], a0l, a1l, a2l, a3l, bhp.x, bhp.y);
                mma_bf16(o[nd], a0h, a1h, a2h, a3h, bhp.x, bhp.y);
            }
        }
        __syncthreads();
    }

    // ---- epilogue: normalize, split, permuted write ----
    float inv0 = 1.0f / lsum0;
    float inv1 = 1.0f / lsum1;
    size_t row0 = (size_t)(b * Sq + qt * 128 + m0 + g);
    #pragma unroll
    for (int nd = 0; nd < 16; nd++) {
        int wp = permw(h * (Dd/2) + nd * 4 + tig);
        unsigned hh, llw;
        split2(o[nd][0] * inv0, o[nd][1] * inv0, hh, llw);
        g_a_hi[row0 * (HID/2) + wp] = hh;
        g_a_lo[row0 * (HID/2) + wp] = llw;
        split2(o[nd][2] * inv1, o[nd][3] * inv1, hh, llw);
        g_a_hi[(row0 + 8) * (HID/2) + wp] = hh;
        g_a_lo[(row0 + 8) * (HID/2) + wp] = llw;
    }
}

// ---------------------------------------------------------------------------
// KV cache broadcast
// ---------------------------------------------------------------------------
__global__ __launch_bounds__(256)
void kv_broadcast(float* __restrict__ out)
{
    int i = blockIdx.x * 256 + threadIdx.x;
    int o = i * 4;
    int b = o / (Sq * Dd);
    int rem = o - b * Sq * Dd;
    int s = rem / Dd;
    int d = rem - s * Dd;
    float4 kv = *(const float4*)&g_k[o];
    float4 vv = *(const float4*)&g_v[o];
    const size_t keybase = (size_t)MM * HID;
    const size_t valbase = keybase + (size_t)Bz * Hh * Sq * Dd;
    #pragma unroll
    for (int h = 0; h < Hh; h++) {
        size_t idx = (((size_t)b * Hh + h) * Sq + s) * Dd + d;
        *(float4*)&out[keybase + idx] = kv;
        *(float4*)&out[valbase + idx] = vv;
    }
}

// ---------------------------------------------------------------------------
extern "C" void kernel_launch(void* const* d_in, const int* in_sizes, int n_in,
                              void* d_out, int out_size)
{
    const float* hs   = (const float*)d_in[0];
    const float* mask = (const float*)d_in[1];
    const float* Wq   = (const float*)d_in[2];
    const float* Wk   = (const float*)d_in[3];
    const float* Wv   = (const float*)d_in[4];
    const float* Wo   = (const float*)d_in[5];
    float* out = (float*)d_out;

    void *hsh, *hsl, *wqh, *wql, *wkh, *wkl, *wvh, *wvl, *woh, *wol;
    cudaGetSymbolAddress(&hsh, g_hs_hi);  cudaGetSymbolAddress(&hsl, g_hs_lo);
    cudaGetSymbolAddress(&wqh, g_wq_hi);  cudaGetSymbolAddress(&wql, g_wq_lo);
    cudaGetSymbolAddress(&wkh, g_wk_hi);  cudaGetSymbolAddress(&wkl, g_wk_lo);
    cudaGetSymbolAddress(&wvh, g_wv_hi);  cudaGetSymbolAddress(&wvl, g_wv_lo);
    cudaGetSymbolAddress(&woh, g_wo_hi);  cudaGetSymbolAddress(&wol, g_wo_lo);

    cudaFuncSetAttribute(attn_kernel, cudaFuncAttributeMaxDynamicSharedMemorySize,
                         ATTN_SMEM_WORDS * 4);
    cudaFuncSetAttribute(gemm_q2,  cudaFuncAttributeMaxDynamicSharedMemorySize, GEMM_SMEM_BYTES);
    cudaFuncSetAttribute(gemm_kv2, cudaFuncAttributeMaxDynamicSharedMemorySize, GEMM_SMEM_BYTES);
    cudaFuncSetAttribute(gemm_o2,  cudaFuncAttributeMaxDynamicSharedMemorySize, GEMM_SMEM_BYTES);

    dim3 blk(256);
    // presplit inputs (permuted hi/lo word layout)
    presplit<<<MM*HID/16/256,  blk>>>(hs, (unsigned*)hsh, (unsigned*)hsl, MM*HID/16);
    presplit<<<HID*HID/16/256, blk>>>(Wq, (unsigned*)wqh, (unsigned*)wql, HID*HID/16);
    presplit<<<Dd*HID/16/256,  blk>>>(Wk, (unsigned*)wkh, (unsigned*)wkl, Dd*HID/16);
    presplit<<<Dd*HID/16/256,  blk>>>(Wv, (unsigned*)wvh, (unsigned*)wvl, Dd*HID/16);
    presplit<<<HID*HID/16/256, blk>>>(Wo, (unsigned*)woh, (unsigned*)wol, HID*HID/16);

    // projections
    gemm_q2 <<<dim3(HID / BN, MM / BM),    blk, GEMM_SMEM_BYTES>>>(MM, HID, HID);
    gemm_kv2<<<dim3(1, MM / BM, 2),        blk, GEMM_SMEM_BYTES>>>(MM, Dd, HID);
    // KV cache broadcast
    kv_broadcast<<<(MM * Dd / 4 + 255) / 256, blk>>>(out);
    // attention
    attn_kernel<<<dim3(Sq / 128, Bz * Hh), blk, ATTN_SMEM_WORDS * 4>>>(mask);
    // output projection
    gemm_o2 <<<dim3(HID / BN, MM / BM),    blk, GEMM_SMEM_BYTES>>>(out, MM, HID, HID);
}